// round 1
// baseline (speedup 1.0000x reference)
#include <cuda_runtime.h>

#define NCLU 64
#define NDIM 64
#define TILE 64
#define THREADS 256
#define GRID 592   // ~4 blocks/SM * 148 SMs

// device-global state (no allocations allowed)
__device__ float g_C[2][NCLU * NDIM];
__device__ float g_num[NCLU * NDIM];
__device__ float g_den[NCLU];
__device__ int   g_done;

__global__ void fcm_zero() {
    int t = threadIdx.x;
    for (int i = t; i < NCLU * NDIM; i += THREADS) g_num[i] = 0.f;
    if (t < NCLU) g_den[t] = 0.f;
    if (t == 0) g_done = 0;
}

// Fused pass:
//  mode==1: given C (g_C[pp]), compute per-row membership U' from distances,
//           accumulate (U'^2)^T @ X and colsum(U'^2) into g_num/g_den.
//  mode==0: same accumulation but U from normalized u0_raw (initial center).
__global__ void fcm_pass(const float* __restrict__ data,
                         const float* __restrict__ u0raw,
                         int N, int pp, int mode) {
    extern __shared__ float smem[];
    float* Xs   = smem;             // [64][64] X row-major
    float* XtW  = smem + 4096;      // X^T (phase1) then w / Um row-major
    float* Ct   = smem + 8192;      // [d][j] C transposed
    float* x2   = smem + 12288;     // [64]
    float* c2   = x2 + 64;          // [64]
    float* wsum = c2 + 64;          // [64]

    const int t  = threadIdx.x;
    const int r0 = (t >> 4) << 2;   // row-group (phase1) / j-group (phase2)
    const int q0 = (t & 15) << 2;   // j-group (phase1) / d-group (phase2)

    if (mode) {
        const float* C = g_C[pp];
        for (int i = t; i < 4096; i += THREADS) {
            int j = i >> 6, d = i & 63;
            Ct[d * 64 + j] = C[i];
        }
        __syncthreads();
        if (t < 64) {
            float s = 0.f;
            #pragma unroll 8
            for (int d = 0; d < 64; d++) { float v = Ct[d * 64 + t]; s += v * v; }
            c2[t] = s;
        }
    }

    float acc[4][4];
    #pragma unroll
    for (int i = 0; i < 4; i++)
        #pragma unroll
        for (int k = 0; k < 4; k++) acc[i][k] = 0.f;
    float dacc[4] = {0.f, 0.f, 0.f, 0.f};

    const int ntiles = (N + TILE - 1) / TILE;
    for (int tile = blockIdx.x; tile < ntiles; tile += gridDim.x) {
        __syncthreads();  // protect shared reuse across tiles (and c2 setup on first)
        const int row0  = tile * TILE;
        const int nrows = min(TILE, N - row0);

        // load X tile (row-major; also transposed copy when mode==1)
        for (int i = t; i < 1024; i += THREADS) {
            int r = i >> 4, dq = (i & 15);
            float4 v;
            if (r < nrows)
                v = reinterpret_cast<const float4*>(data + (size_t)(row0 + r) * 64)[dq];
            else
                v = make_float4(0.f, 0.f, 0.f, 0.f);
            reinterpret_cast<float4*>(Xs + r * 64)[dq] = v;
            if (mode) {
                int d = dq << 2;
                XtW[(d + 0) * 64 + r] = v.x;
                XtW[(d + 1) * 64 + r] = v.y;
                XtW[(d + 2) * 64 + r] = v.z;
                XtW[(d + 3) * 64 + r] = v.w;
            }
        }
        if (!mode) {
            for (int i = t; i < 1024; i += THREADS) {
                int r = i >> 4, dq = (i & 15);
                float4 v;
                if (r < nrows)
                    v = reinterpret_cast<const float4*>(u0raw + (size_t)(row0 + r) * 64)[dq];
                else
                    v = make_float4(0.f, 0.f, 0.f, 0.f);
                reinterpret_cast<float4*>(XtW + r * 64)[dq] = v;
            }
        }
        __syncthreads();

        if (mode) {
            // row squared norms (rotated index: conflict-free)
            if (t < 64) {
                float s = 0.f;
                #pragma unroll 8
                for (int d = 0; d < 64; d++) {
                    float v = Xs[t * 64 + ((d + t) & 63)];
                    s += v * v;
                }
                x2[t] = s;
            }
            // phase 1: S[r][j] = x_r . c_j   (4x4 register tile per thread)
            float S[4][4];
            #pragma unroll
            for (int i = 0; i < 4; i++)
                #pragma unroll
                for (int k = 0; k < 4; k++) S[i][k] = 0.f;
            #pragma unroll 8
            for (int d = 0; d < 64; d++) {
                float4 xv = *reinterpret_cast<const float4*>(&XtW[d * 64 + r0]);
                float4 cv = *reinterpret_cast<const float4*>(&Ct[d * 64 + q0]);
                float xr[4] = {xv.x, xv.y, xv.z, xv.w};
                float cr[4] = {cv.x, cv.y, cv.z, cv.w};
                #pragma unroll
                for (int i = 0; i < 4; i++)
                    #pragma unroll
                    for (int k = 0; k < 4; k++) S[i][k] = fmaf(xr[i], cr[k], S[i][k]);
            }
            __syncthreads();  // all reads of XtW (X^T) and x2 writes complete

            // w = 1 / max(x2 + c2 - 2*S, 0)
            #pragma unroll
            for (int i = 0; i < 4; i++) {
                float xx = x2[r0 + i];
                #pragma unroll
                for (int k = 0; k < 4; k++) {
                    float dist = fmaxf(fmaf(-2.f, S[i][k], xx + c2[q0 + k]), 0.f);
                    float w = 1.f / dist;
                    S[i][k] = w;
                    XtW[(r0 + i) * 64 + (q0 + k)] = w;
                }
            }
            __syncthreads();
            if (t < 64) {
                float s = 0.f;
                #pragma unroll 8
                for (int j = 0; j < 64; j++) s += XtW[t * 64 + ((j + t) & 63)];
                wsum[t] = s;
            }
            __syncthreads();
            // Um = (w / wsum)^2 (zero for padded rows)
            #pragma unroll
            for (int i = 0; i < 4; i++) {
                float inv = 1.f / wsum[r0 + i];
                bool valid = (r0 + i) < nrows;
                #pragma unroll
                for (int k = 0; k < 4; k++) {
                    float u = S[i][k] * inv;
                    XtW[(r0 + i) * 64 + (q0 + k)] = valid ? u * u : 0.f;
                }
            }
            __syncthreads();
        } else {
            // Um from normalized u0_raw
            if (t < 64) {
                float s = 0.f;
                #pragma unroll 8
                for (int j = 0; j < 64; j++) s += XtW[t * 64 + ((j + t) & 63)];
                wsum[t] = s;
            }
            __syncthreads();
            for (int i = t; i < 4096; i += THREADS) {
                int r = i >> 6;
                float u = XtW[i] / wsum[r];
                XtW[i] = (r < nrows) ? u * u : 0.f;
            }
            __syncthreads();
        }

        // phase 2: acc[j][d] += sum_r Um[r][j] * X[r][d]
        #pragma unroll 8
        for (int r = 0; r < 64; r++) {
            float4 um = *reinterpret_cast<const float4*>(&XtW[r * 64 + r0]);
            float4 xv = *reinterpret_cast<const float4*>(&Xs[r * 64 + q0]);
            float ur[4] = {um.x, um.y, um.z, um.w};
            float xr[4] = {xv.x, xv.y, xv.z, xv.w};
            #pragma unroll
            for (int i = 0; i < 4; i++)
                #pragma unroll
                for (int k = 0; k < 4; k++) acc[i][k] = fmaf(ur[i], xr[k], acc[i][k]);
            if ((t & 15) == 0) {
                dacc[0] += um.x; dacc[1] += um.y; dacc[2] += um.z; dacc[3] += um.w;
            }
        }
    }

    // flush register accumulators (one atomic per owned element)
    #pragma unroll
    for (int i = 0; i < 4; i++)
        #pragma unroll
        for (int k = 0; k < 4; k++)
            atomicAdd(&g_num[(r0 + i) * 64 + (q0 + k)], acc[i][k]);
    if ((t & 15) == 0) {
        #pragma unroll
        for (int i = 0; i < 4; i++) atomicAdd(&g_den[r0 + i], dacc[i]);
    }
}

// Compute C_new = num/den into g_C[pnew]; if do_diff: latch logic vs g_C[pnew^1].
__global__ void fcm_center(float* __restrict__ out, int pnew, int do_diff) {
    __shared__ float red[THREADS];
    const int t = threadIdx.x;
    const int done = g_done;
    float local = 0.f;
    float* Cn = g_C[pnew];
    const float* Cp = g_C[pnew ^ 1];
    for (int i = t; i < 4096; i += THREADS) {
        float c = g_num[i] / g_den[i >> 6];
        Cn[i] = c;
        g_num[i] = 0.f;
        if (do_diff) {
            float p = Cp[i];
            float dd = c - p;
            local += dd * dd;
            if (!done) out[i] = p;   // out tracks C_{k-1}; frozen once done
        }
    }
    __syncthreads();                 // all reads of g_den complete
    if (t < NCLU) g_den[t] = 0.f;
    if (do_diff) {
        red[t] = local;
        __syncthreads();
        #pragma unroll
        for (int s = 128; s > 0; s >>= 1) {
            if (t < s) red[t] += red[t + s];
            __syncthreads();
        }
        if (t == 0 && !done && sqrtf(red[0]) < 1e-8f) g_done = 1;
    }
}

__global__ void fcm_final(float* __restrict__ out, int plast) {
    if (g_done) return;
    const int t = threadIdx.x;
    for (int i = t; i < 4096; i += THREADS) out[i] = g_C[plast][i];
}

extern "C" void kernel_launch(void* const* d_in, const int* in_sizes, int n_in,
                              void* d_out, int out_size) {
    const float* data = (const float*)d_in[0];
    const float* u0   = (const float*)d_in[1];
    const int N = in_sizes[0] / NDIM;   // 300000
    float* out = (float*)d_out;

    const size_t SMEM = (size_t)(3 * 4096 + 192) * sizeof(float);  // 49920 B
    cudaFuncSetAttribute(fcm_pass, cudaFuncAttributeMaxDynamicSharedMemorySize, (int)SMEM);

    fcm_zero<<<1, THREADS>>>();
    // C_0 = center(U_0) from u0_raw
    fcm_pass<<<GRID, THREADS, SMEM>>>(data, u0, N, 0, 0);
    fcm_center<<<1, THREADS>>>(out, 0, 0);
    // iterations: C_i from C_{i-1}, with convergence latch on ||C_i - C_{i-1}||_F
    for (int i = 1; i <= 25; i++) {
        fcm_pass<<<GRID, THREADS, SMEM>>>(data, u0, N, (i - 1) & 1, 1);
        fcm_center<<<1, THREADS>>>(out, i & 1, 1);
    }
    // if never converged, answer is C_25
    fcm_final<<<1, THREADS>>>(out, 25 & 1);
}

// round 2
// speedup vs baseline: 1.0003x; 1.0003x over previous
#include <cuda_runtime.h>

#define NCLU 64
#define NDIM 64
#define TILE 64
#define THREADS 256
#define GRID 592   // ~4 blocks/SM * 148 SMs

// device-global state (no allocations allowed)
__device__ float g_C[2][NCLU * NDIM];
__device__ float g_num[NCLU * NDIM];
__device__ float g_den[NCLU];
__device__ int   g_done;

__global__ void fcm_zero() {
    int t = threadIdx.x;
    for (int i = t; i < NCLU * NDIM; i += THREADS) g_num[i] = 0.f;
    if (t < NCLU) g_den[t] = 0.f;
    if (t == 0) g_done = 0;
}

// Fused pass:
//  mode==1: given C (g_C[pp]), compute per-row membership U' from distances,
//           accumulate (U'^2)^T @ X and colsum(U'^2) into g_num/g_den.
//  mode==0: same accumulation but U from normalized u0_raw (initial center).
__global__ void fcm_pass(const float* __restrict__ data,
                         const float* __restrict__ u0raw,
                         int N, int pp, int mode) {
    extern __shared__ float smem[];
    float* Xs   = smem;             // [64][64] X row-major
    float* XtW  = smem + 4096;      // X^T (phase1) then w / Um row-major
    float* Ct   = smem + 8192;      // [d][j] C transposed
    float* x2   = smem + 12288;     // [64]
    float* c2   = x2 + 64;          // [64]
    float* wsum = c2 + 64;          // [64]

    const int t  = threadIdx.x;
    const int r0 = (t >> 4) << 2;   // row-group (phase1) / j-group (phase2)
    const int q0 = (t & 15) << 2;   // j-group (phase1) / d-group (phase2)

    if (mode) {
        const float* C = g_C[pp];
        for (int i = t; i < 4096; i += THREADS) {
            int j = i >> 6, d = i & 63;
            Ct[d * 64 + j] = C[i];
        }
        __syncthreads();
        if (t < 64) {
            float s = 0.f;
            #pragma unroll 8
            for (int d = 0; d < 64; d++) { float v = Ct[d * 64 + t]; s += v * v; }
            c2[t] = s;
        }
    }

    float acc[4][4];
    #pragma unroll
    for (int i = 0; i < 4; i++)
        #pragma unroll
        for (int k = 0; k < 4; k++) acc[i][k] = 0.f;
    float dacc[4] = {0.f, 0.f, 0.f, 0.f};

    const int ntiles = (N + TILE - 1) / TILE;
    for (int tile = blockIdx.x; tile < ntiles; tile += gridDim.x) {
        __syncthreads();  // protect shared reuse across tiles (and c2 setup on first)
        const int row0  = tile * TILE;
        const int nrows = min(TILE, N - row0);

        // load X tile (row-major; also transposed copy when mode==1)
        for (int i = t; i < 1024; i += THREADS) {
            int r = i >> 4, dq = (i & 15);
            float4 v;
            if (r < nrows)
                v = reinterpret_cast<const float4*>(data + (size_t)(row0 + r) * 64)[dq];
            else
                v = make_float4(0.f, 0.f, 0.f, 0.f);
            reinterpret_cast<float4*>(Xs + r * 64)[dq] = v;
            if (mode) {
                int d = dq << 2;
                XtW[(d + 0) * 64 + r] = v.x;
                XtW[(d + 1) * 64 + r] = v.y;
                XtW[(d + 2) * 64 + r] = v.z;
                XtW[(d + 3) * 64 + r] = v.w;
            }
        }
        if (!mode) {
            for (int i = t; i < 1024; i += THREADS) {
                int r = i >> 4, dq = (i & 15);
                float4 v;
                if (r < nrows)
                    v = reinterpret_cast<const float4*>(u0raw + (size_t)(row0 + r) * 64)[dq];
                else
                    v = make_float4(0.f, 0.f, 0.f, 0.f);
                reinterpret_cast<float4*>(XtW + r * 64)[dq] = v;
            }
        }
        __syncthreads();

        if (mode) {
            // row squared norms (rotated index: conflict-free)
            if (t < 64) {
                float s = 0.f;
                #pragma unroll 8
                for (int d = 0; d < 64; d++) {
                    float v = Xs[t * 64 + ((d + t) & 63)];
                    s += v * v;
                }
                x2[t] = s;
            }
            // phase 1: S[r][j] = x_r . c_j   (4x4 register tile per thread)
            float S[4][4];
            #pragma unroll
            for (int i = 0; i < 4; i++)
                #pragma unroll
                for (int k = 0; k < 4; k++) S[i][k] = 0.f;
            #pragma unroll 8
            for (int d = 0; d < 64; d++) {
                float4 xv = *reinterpret_cast<const float4*>(&XtW[d * 64 + r0]);
                float4 cv = *reinterpret_cast<const float4*>(&Ct[d * 64 + q0]);
                float xr[4] = {xv.x, xv.y, xv.z, xv.w};
                float cr[4] = {cv.x, cv.y, cv.z, cv.w};
                #pragma unroll
                for (int i = 0; i < 4; i++)
                    #pragma unroll
                    for (int k = 0; k < 4; k++) S[i][k] = fmaf(xr[i], cr[k], S[i][k]);
            }
            __syncthreads();  // all reads of XtW (X^T) and x2 writes complete

            // w = 1 / max(x2 + c2 - 2*S, 0)
            #pragma unroll
            for (int i = 0; i < 4; i++) {
                float xx = x2[r0 + i];
                #pragma unroll
                for (int k = 0; k < 4; k++) {
                    float dist = fmaxf(fmaf(-2.f, S[i][k], xx + c2[q0 + k]), 0.f);
                    float w = 1.f / dist;
                    S[i][k] = w;
                    XtW[(r0 + i) * 64 + (q0 + k)] = w;
                }
            }
            __syncthreads();
            if (t < 64) {
                float s = 0.f;
                #pragma unroll 8
                for (int j = 0; j < 64; j++) s += XtW[t * 64 + ((j + t) & 63)];
                wsum[t] = s;
            }
            __syncthreads();
            // Um = (w / wsum)^2 (zero for padded rows)
            #pragma unroll
            for (int i = 0; i < 4; i++) {
                float inv = 1.f / wsum[r0 + i];
                bool valid = (r0 + i) < nrows;
                #pragma unroll
                for (int k = 0; k < 4; k++) {
                    float u = S[i][k] * inv;
                    XtW[(r0 + i) * 64 + (q0 + k)] = valid ? u * u : 0.f;
                }
            }
            __syncthreads();
        } else {
            // Um from normalized u0_raw
            if (t < 64) {
                float s = 0.f;
                #pragma unroll 8
                for (int j = 0; j < 64; j++) s += XtW[t * 64 + ((j + t) & 63)];
                wsum[t] = s;
            }
            __syncthreads();
            for (int i = t; i < 4096; i += THREADS) {
                int r = i >> 6;
                float u = XtW[i] / wsum[r];
                XtW[i] = (r < nrows) ? u * u : 0.f;
            }
            __syncthreads();
        }

        // phase 2: acc[j][d] += sum_r Um[r][j] * X[r][d]
        #pragma unroll 8
        for (int r = 0; r < 64; r++) {
            float4 um = *reinterpret_cast<const float4*>(&XtW[r * 64 + r0]);
            float4 xv = *reinterpret_cast<const float4*>(&Xs[r * 64 + q0]);
            float ur[4] = {um.x, um.y, um.z, um.w};
            float xr[4] = {xv.x, xv.y, xv.z, xv.w};
            #pragma unroll
            for (int i = 0; i < 4; i++)
                #pragma unroll
                for (int k = 0; k < 4; k++) acc[i][k] = fmaf(ur[i], xr[k], acc[i][k]);
            if ((t & 15) == 0) {
                dacc[0] += um.x; dacc[1] += um.y; dacc[2] += um.z; dacc[3] += um.w;
            }
        }
    }

    // flush register accumulators (one atomic per owned element)
    #pragma unroll
    for (int i = 0; i < 4; i++)
        #pragma unroll
        for (int k = 0; k < 4; k++)
            atomicAdd(&g_num[(r0 + i) * 64 + (q0 + k)], acc[i][k]);
    if ((t & 15) == 0) {
        #pragma unroll
        for (int i = 0; i < 4; i++) atomicAdd(&g_den[r0 + i], dacc[i]);
    }
}

// Compute C_new = num/den into g_C[pnew]; if do_diff: latch logic vs g_C[pnew^1].
__global__ void fcm_center(float* __restrict__ out, int pnew, int do_diff) {
    __shared__ float red[THREADS];
    const int t = threadIdx.x;
    const int done = g_done;
    float local = 0.f;
    float* Cn = g_C[pnew];
    const float* Cp = g_C[pnew ^ 1];
    for (int i = t; i < 4096; i += THREADS) {
        float c = g_num[i] / g_den[i >> 6];
        Cn[i] = c;
        g_num[i] = 0.f;
        if (do_diff) {
            float p = Cp[i];
            float dd = c - p;
            local += dd * dd;
            if (!done) out[i] = p;   // out tracks C_{k-1}; frozen once done
        }
    }
    __syncthreads();                 // all reads of g_den complete
    if (t < NCLU) g_den[t] = 0.f;
    if (do_diff) {
        red[t] = local;
        __syncthreads();
        #pragma unroll
        for (int s = 128; s > 0; s >>= 1) {
            if (t < s) red[t] += red[t + s];
            __syncthreads();
        }
        if (t == 0 && !done && sqrtf(red[0]) < 1e-8f) g_done = 1;
    }
}

__global__ void fcm_final(float* __restrict__ out, int plast) {
    if (g_done) return;
    const int t = threadIdx.x;
    for (int i = t; i < 4096; i += THREADS) out[i] = g_C[plast][i];
}

extern "C" void kernel_launch(void* const* d_in, const int* in_sizes, int n_in,
                              void* d_out, int out_size) {
    const float* data = (const float*)d_in[0];
    const float* u0   = (const float*)d_in[1];
    const int N = in_sizes[0] / NDIM;   // 300000
    float* out = (float*)d_out;

    const size_t SMEM = (size_t)(3 * 4096 + 192) * sizeof(float);  // 49920 B
    cudaFuncSetAttribute(fcm_pass, cudaFuncAttributeMaxDynamicSharedMemorySize, (int)SMEM);

    fcm_zero<<<1, THREADS>>>();
    // C_0 = center(U_0) from u0_raw
    fcm_pass<<<GRID, THREADS, SMEM>>>(data, u0, N, 0, 0);
    fcm_center<<<1, THREADS>>>(out, 0, 0);
    // iterations: C_i from C_{i-1}, with convergence latch on ||C_i - C_{i-1}||_F
    for (int i = 1; i <= 25; i++) {
        fcm_pass<<<GRID, THREADS, SMEM>>>(data, u0, N, (i - 1) & 1, 1);
        fcm_center<<<1, THREADS>>>(out, i & 1, 1);
    }
    // if never converged, answer is C_25
    fcm_final<<<1, THREADS>>>(out, 25 & 1);
}

// round 4
// speedup vs baseline: 2.5394x; 2.5386x over previous
#include <cuda_runtime.h>
#include <cuda_fp16.h>
#include <cstdint>

#define THREADS 256
#define GRIDSZ  296
#define NBUCKET 16

// ---------------- device-global state (no allocations allowed) ----------------
__device__ float g_C[2][64 * 64];
__device__ float g_part[NBUCKET][64 * 64];
__device__ float g_denp[NBUCKET][64];
__device__ int   g_done;

// ---------------- smem layout (bytes) ----------------
#define OFF_XH  0        // [128][64] half, swizzled, 16 KB
#define OFF_XL  16384
#define OFF_UH  32768    // [128 r][64 j] half, swizzled, 16 KB
#define OFF_UL  49152
#define OFF_CH  65536    // [64][64] half, 8 KB
#define OFF_CL  73728
#define OFF_X2  81920    // float[128]
#define OFF_C2  82432    // float[64]
#define SMEM_BYTES 82688

// XOR swizzle: 16B-chunk permutation within a 128B row (conflict-free ldmatrix)
static __device__ __forceinline__ uint32_t swz(int r, int colhalf) {
    return (uint32_t)(r * 128 + ((colhalf * 2) ^ ((r & 7) << 4)));
}

static __device__ __forceinline__ uint32_t smem_u32(const void* p) {
    uint32_t a;
    asm("{ .reg .u64 t; cvta.to.shared.u64 t, %1; cvt.u32.u64 %0, t; }" : "=r"(a) : "l"(p));
    return a;
}

// ---------------- mma / ldmatrix wrappers (sm_80+ features, no 'a' target) ----
static __device__ __forceinline__ void ldsm4(uint32_t* r, uint32_t a) {
    asm volatile("ldmatrix.sync.aligned.m8n8.x4.shared.b16 {%0,%1,%2,%3}, [%4];"
                 : "=r"(r[0]), "=r"(r[1]), "=r"(r[2]), "=r"(r[3]) : "r"(a));
}
static __device__ __forceinline__ void ldsm4t(uint32_t* r, uint32_t a) {
    asm volatile("ldmatrix.sync.aligned.m8n8.x4.trans.shared.b16 {%0,%1,%2,%3}, [%4];"
                 : "=r"(r[0]), "=r"(r[1]), "=r"(r[2]), "=r"(r[3]) : "r"(a));
}
static __device__ __forceinline__ void ldsm2(uint32_t* r, uint32_t a) {
    asm volatile("ldmatrix.sync.aligned.m8n8.x2.shared.b16 {%0,%1}, [%2];"
                 : "=r"(r[0]), "=r"(r[1]) : "r"(a));
}
static __device__ __forceinline__ void ldsm2t(uint32_t* r, uint32_t a) {
    asm volatile("ldmatrix.sync.aligned.m8n8.x2.trans.shared.b16 {%0,%1}, [%2];"
                 : "=r"(r[0]), "=r"(r[1]) : "r"(a));
}
static __device__ __forceinline__ void mma16816(float* d, const uint32_t* a, const uint32_t* b) {
    asm volatile("mma.sync.aligned.m16n8k16.row.col.f32.f16.f16.f32 "
                 "{%0,%1,%2,%3}, {%4,%5,%6,%7}, {%8,%9}, {%0,%1,%2,%3};"
                 : "+f"(d[0]), "+f"(d[1]), "+f"(d[2]), "+f"(d[3])
                 : "r"(a[0]), "r"(a[1]), "r"(a[2]), "r"(a[3]), "r"(b[0]), "r"(b[1]));
}

static __device__ __forceinline__ uint32_t packh2(half a, half b) {
    half2 h = __halves2half2(a, b);
    return *reinterpret_cast<uint32_t*>(&h);
}

// ---------------- fused pass ----------------
__global__ void __launch_bounds__(THREADS, 2)
fcm_pass_mma(const float* __restrict__ data, const float* __restrict__ u0,
             int N, int pp, int mode)
{
    extern __shared__ char smem[];
    const uint32_t sb = smem_u32(smem);
    float* x2s = (float*)(smem + OFF_X2);
    float* c2s = (float*)(smem + OFF_C2);

    const int t = threadIdx.x;
    const int w = t >> 5, lane = t & 31;
    const int quad = lane >> 2, qid = lane & 3;
    const int bucket = blockIdx.x & (NBUCKET - 1);

    // C hi/lo tiles + c2 (mode 1 only)
    if (mode) {
        const float* C = g_C[pp];
        for (int i = t; i < 4096; i += THREADS) {
            int j = i >> 6, d = i & 63;
            float v = C[i];
            half h = __float2half_rn(v);
            half l = __float2half_rn(v - __half2float(h));
            uint32_t off = swz(j, d);
            *(half*)(smem + OFF_CH + off) = h;
            *(half*)(smem + OFF_CL + off) = l;
        }
        if (t < 64) {
            const float* Cr = g_C[pp] + t * 64;
            float s = 0.f;
            #pragma unroll 8
            for (int d = 0; d < 64; d++) s += Cr[d] * Cr[d];
            c2s[t] = s;
        }
    }

    float G[4][4];
    #pragma unroll
    for (int a = 0; a < 4; a++)
        #pragma unroll
        for (int b = 0; b < 4; b++) G[a][b] = 0.f;
    float DEN[4] = {0.f, 0.f, 0.f, 0.f};

    const int ntiles = (N + 127) >> 7;
    const int jm = (w & 3) * 16;        // GEMM2 m-tile (j rows)
    const int nb = (w >> 2) * 4;        // GEMM2 n-tile base (d)

    for (int tile = blockIdx.x; tile < ntiles; tile += gridDim.x) {
        __syncthreads();   // previous GEMM2 reads of X/U done

        // ---- load X tile: fp32 -> swizzled fp16 hi/lo + exact fp32 row norms ----
        #pragma unroll
        for (int it = 0; it < 4; it++) {
            int i = t + it * THREADS;          // 0..1023
            int r = i >> 3, c = i & 7;         // row, 8-half chunk
            int grow = tile * 128 + r;
            float4 v0 = make_float4(0.f, 0.f, 0.f, 0.f), v1 = v0;
            if (grow < N) {
                const float4* p = reinterpret_cast<const float4*>(data + (size_t)grow * 64 + c * 8);
                v0 = p[0]; v1 = p[1];
            }
            float f[8] = {v0.x, v0.y, v0.z, v0.w, v1.x, v1.y, v1.z, v1.w};
            uint32_t hp[4], lp[4];
            #pragma unroll
            for (int k = 0; k < 4; k++) {
                half h0 = __float2half_rn(f[2*k]),   h1 = __float2half_rn(f[2*k+1]);
                half l0 = __float2half_rn(f[2*k]   - __half2float(h0));
                half l1 = __float2half_rn(f[2*k+1] - __half2float(h1));
                hp[k] = packh2(h0, h1);
                lp[k] = packh2(l0, l1);
            }
            uint32_t off = swz(r, c * 8);
            *reinterpret_cast<uint4*>(smem + OFF_XH + off) = make_uint4(hp[0], hp[1], hp[2], hp[3]);
            *reinterpret_cast<uint4*>(smem + OFF_XL + off) = make_uint4(lp[0], lp[1], lp[2], lp[3]);
            float sq = 0.f;
            #pragma unroll
            for (int k = 0; k < 8; k++) sq += f[k] * f[k];
            sq += __shfl_xor_sync(0xFFFFFFFFu, sq, 1);
            sq += __shfl_xor_sync(0xFFFFFFFFu, sq, 2);
            sq += __shfl_xor_sync(0xFFFFFFFFu, sq, 4);
            if (c == 0) x2s[r] = sq;
        }
        __syncthreads();

        // ---- memberships: S regs become w, then u^2 ----
        float S[8][4];
        const int r1l = 16 * w + quad;     // local rows this thread owns
        const int grow1 = tile * 128 + r1l;
        const int grow2 = grow1 + 8;

        if (mode) {
            #pragma unroll
            for (int tn = 0; tn < 8; tn++)
                #pragma unroll
                for (int b = 0; b < 4; b++) S[tn][b] = 0.f;
            // GEMM1: S = Xh.Ch^T + Xh.Cl^T + Xl.Ch^T  (warp w: rows 16w..16w+15)
            const int seg = lane >> 3, q = lane & 7;
            #pragma unroll
            for (int kk = 0; kk < 4; kk++) {
                int ar = 16 * w + (seg & 1) * 8 + q;
                int ac = kk * 16 + (seg >> 1) * 8;
                uint32_t aoff = sb + swz(ar, ac);
                uint32_t ah[4], al[4];
                ldsm4(ah, aoff + OFF_XH);
                ldsm4(al, aoff + OFF_XL);
                int br = (seg & 1) ? (q + 8) : q;   // dummy-safe; real rows below
                (void)br;
                #pragma unroll
                for (int tn = 0; tn < 8; tn++) {
                    int bj = 8 * tn + q;
                    int bc = kk * 16 + ((lane >> 3) & 1) * 8;
                    uint32_t boff = sb + swz(bj, bc);
                    uint32_t bh[2], bl[2];
                    ldsm2(bh, boff + OFF_CH);
                    ldsm2(bl, boff + OFF_CL);
                    mma16816(S[tn], ah, bh);
                    mma16816(S[tn], ah, bl);
                    mma16816(S[tn], al, bh);
                }
            }
            // S -> w = 1/max(x2+c2-2S, 0)
            float xx1 = x2s[r1l], xx2 = x2s[r1l + 8];
            #pragma unroll
            for (int tn = 0; tn < 8; tn++) {
                int j = 8 * tn + qid * 2;
                float ca = c2s[j], cb = c2s[j + 1];
                S[tn][0] = 1.f / fmaxf(xx1 + ca - 2.f * S[tn][0], 0.f);
                S[tn][1] = 1.f / fmaxf(xx1 + cb - 2.f * S[tn][1], 0.f);
                S[tn][2] = 1.f / fmaxf(xx2 + ca - 2.f * S[tn][2], 0.f);
                S[tn][3] = 1.f / fmaxf(xx2 + cb - 2.f * S[tn][3], 0.f);
            }
        } else {
            // initial U from u0_raw
            #pragma unroll
            for (int tn = 0; tn < 8; tn++) {
                int j = 8 * tn + qid * 2;
                float2 p1 = make_float2(0.f, 0.f), p2 = p1;
                if (grow1 < N) p1 = *reinterpret_cast<const float2*>(u0 + (size_t)grow1 * 64 + j);
                if (grow2 < N) p2 = *reinterpret_cast<const float2*>(u0 + (size_t)grow2 * 64 + j);
                S[tn][0] = p1.x; S[tn][1] = p1.y; S[tn][2] = p2.x; S[tn][3] = p2.y;
            }
        }

        // row sums across the 4-lane quad
        float s1 = 0.f, s2 = 0.f;
        #pragma unroll
        for (int tn = 0; tn < 8; tn++) { s1 += S[tn][0] + S[tn][1]; s2 += S[tn][2] + S[tn][3]; }
        s1 += __shfl_xor_sync(0xFFFFFFFFu, s1, 1);
        s1 += __shfl_xor_sync(0xFFFFFFFFu, s1, 2);
        s2 += __shfl_xor_sync(0xFFFFFFFFu, s2, 1);
        s2 += __shfl_xor_sync(0xFFFFFFFFu, s2, 2);
        float i1 = (grow1 < N) ? 1.f / s1 : 0.f;
        float i2 = (grow2 < N) ? 1.f / s2 : 0.f;

        // u^2 -> fp16 hi/lo -> smem U tiles
        #pragma unroll
        for (int tn = 0; tn < 8; tn++) {
            int j = 8 * tn + qid * 2;
            float ua0 = S[tn][0] * i1; ua0 *= ua0;
            float ua1 = S[tn][1] * i1; ua1 *= ua1;
            float ub0 = S[tn][2] * i2; ub0 *= ub0;
            float ub1 = S[tn][3] * i2; ub1 *= ub1;
            half ha0 = __float2half_rn(ua0), ha1 = __float2half_rn(ua1);
            half hb0 = __float2half_rn(ub0), hb1 = __float2half_rn(ub1);
            half la0 = __float2half_rn(ua0 - __half2float(ha0));
            half la1 = __float2half_rn(ua1 - __half2float(ha1));
            half lb0 = __float2half_rn(ub0 - __half2float(hb0));
            half lb1 = __float2half_rn(ub1 - __half2float(hb1));
            uint32_t o1 = swz(r1l, j), o2 = swz(r1l + 8, j);
            *(uint32_t*)(smem + OFF_UH + o1) = packh2(ha0, ha1);
            *(uint32_t*)(smem + OFF_UL + o1) = packh2(la0, la1);
            *(uint32_t*)(smem + OFF_UH + o2) = packh2(hb0, hb1);
            *(uint32_t*)(smem + OFF_UL + o2) = packh2(lb0, lb1);
        }
        __syncthreads();

        // ---- GEMM2: G[j][d] += U^T X (3 chains); den += U^T ones (2 chains) ----
        {
            const int seg = lane >> 3, q = lane & 7;
            const uint32_t ones[2] = {0x3C003C00u, 0x3C003C00u};
            #pragma unroll
            for (int rr = 0; rr < 8; rr++) {
                // A = U^T: x4.trans on U[r][j]
                int ur = rr * 16 + (seg >> 1) * 8 + q;
                int uc = jm + (seg & 1) * 8;
                uint32_t uoff = sb + swz(ur, uc);
                uint32_t auh[4], aul[4];
                ldsm4t(auh, uoff + OFF_UH);
                ldsm4t(aul, uoff + OFF_UL);
                #pragma unroll
                for (int tn = 0; tn < 4; tn++) {
                    int d0 = 8 * (nb + tn);
                    int xr = rr * 16 + ((lane >> 3) & 1) * 8 + q;
                    uint32_t xoff = sb + swz(xr, d0);
                    uint32_t bxh[2], bxl[2];
                    ldsm2t(bxh, xoff + OFF_XH);
                    ldsm2t(bxl, xoff + OFF_XL);
                    mma16816(G[tn], auh, bxh);
                    mma16816(G[tn], auh, bxl);
                    mma16816(G[tn], aul, bxh);
                }
                if (w < 4) {
                    mma16816(DEN, auh, ones);
                    mma16816(DEN, aul, ones);
                }
            }
        }
    }

    // ---- flush block partials (bucketed atomics) ----
    {
        int j1 = jm + quad;
        #pragma unroll
        for (int tn = 0; tn < 4; tn++) {
            int d = 8 * (nb + tn) + qid * 2;
            atomicAdd(&g_part[bucket][j1 * 64 + d],       G[tn][0]);
            atomicAdd(&g_part[bucket][j1 * 64 + d + 1],   G[tn][1]);
            atomicAdd(&g_part[bucket][(j1 + 8) * 64 + d],     G[tn][2]);
            atomicAdd(&g_part[bucket][(j1 + 8) * 64 + d + 1], G[tn][3]);
        }
        if (w < 4 && qid == 0) {
            atomicAdd(&g_denp[bucket][j1],     DEN[0]);
            atomicAdd(&g_denp[bucket][j1 + 8], DEN[2]);
        }
    }
}

// ---------------- tiny kernels ----------------
__global__ void fcm_zero() {
    int t = threadIdx.x;
    for (int b = 0; b < NBUCKET; b++) {
        for (int i = t; i < 4096; i += THREADS) g_part[b][i] = 0.f;
        if (t < 64) g_denp[b][t] = 0.f;
    }
    if (t == 0) g_done = 0;
}

__global__ void fcm_center(float* __restrict__ out, int pnew, int do_diff) {
    __shared__ float red[THREADS];
    __shared__ float denS[64];
    const int t = threadIdx.x;
    const int done = g_done;
    if (t < 64) {
        float s = 0.f;
        #pragma unroll
        for (int b = 0; b < NBUCKET; b++) { s += g_denp[b][t]; g_denp[b][t] = 0.f; }
        denS[t] = s;
    }
    __syncthreads();
    float local = 0.f;
    float* Cn = g_C[pnew];
    const float* Cp = g_C[pnew ^ 1];
    for (int i = t; i < 4096; i += THREADS) {
        float num = 0.f;
        #pragma unroll
        for (int b = 0; b < NBUCKET; b++) { num += g_part[b][i]; g_part[b][i] = 0.f; }
        float c = num / denS[i >> 6];
        Cn[i] = c;
        if (do_diff) {
            float p = Cp[i];
            float dd = c - p;
            local += dd * dd;
            if (!done) out[i] = p;   // out tracks C_{k-1}; frozen once done
        }
    }
    if (do_diff) {
        red[t] = local;
        __syncthreads();
        #pragma unroll
        for (int s = 128; s > 0; s >>= 1) {
            if (t < s) red[t] += red[t + s];
            __syncthreads();
        }
        if (t == 0 && !done && sqrtf(red[0]) < 1e-8f) g_done = 1;
    }
}

__global__ void fcm_final(float* __restrict__ out, int plast) {
    if (g_done) return;
    const int t = threadIdx.x;
    for (int i = t; i < 4096; i += THREADS) out[i] = g_C[plast][i];
}

// ---------------- host launch ----------------
extern "C" void kernel_launch(void* const* d_in, const int* in_sizes, int n_in,
                              void* d_out, int out_size) {
    const float* data = (const float*)d_in[0];
    const float* u0   = (const float*)d_in[1];
    const int N = in_sizes[0] / 64;     // 300000
    float* out = (float*)d_out;

    cudaFuncSetAttribute(fcm_pass_mma, cudaFuncAttributeMaxDynamicSharedMemorySize, SMEM_BYTES);

    fcm_zero<<<1, THREADS>>>();
    // C_0 = center(U_0) from u0_raw
    fcm_pass_mma<<<GRIDSZ, THREADS, SMEM_BYTES>>>(data, u0, N, 0, 0);
    fcm_center<<<1, THREADS>>>(out, 0, 0);
    // 25 iterations with convergence latch on ||C_i - C_{i-1}||_F
    for (int i = 1; i <= 25; i++) {
        fcm_pass_mma<<<GRIDSZ, THREADS, SMEM_BYTES>>>(data, u0, N, (i - 1) & 1, 1);
        fcm_center<<<1, THREADS>>>(out, i & 1, 1);
    }
    fcm_final<<<1, THREADS>>>(out, 1);
}

// round 5
// speedup vs baseline: 2.8506x; 1.1226x over previous
#include <cuda_runtime.h>
#include <cuda_fp16.h>
#include <cstdint>

#define THREADS 256
#define GRIDSZ  296
#define NBUCKET 16

// ---------------- device-global state (no allocations allowed) ----------------
__device__ float g_C[2][64 * 64];
__device__ float g_part[NBUCKET][64 * 64];
__device__ float g_denp[NBUCKET][64];
__device__ int   g_done;

// ---------------- smem layout (bytes) ----------------
#define OFF_XH    0        // [128][64] half, swizzled, 16 KB
#define OFF_XL    16384
#define OFF_UH    32768    // [128 r][64 j] half, swizzled, 16 KB
#define OFF_UL    49152
#define OFF_CH    65536    // [64][64] half, 8 KB
#define OFF_STAGE 73728    // [128][64] fp32 raw staging, 32 KB
#define OFF_X2    106496   // float[128]
#define OFF_C2    107008   // float[64]
#define SMEM_BYTES 107264

// XOR swizzle: 16B-chunk permutation within a 128B row (conflict-free ldmatrix)
static __device__ __forceinline__ uint32_t swz(int r, int colhalf) {
    return (uint32_t)(r * 128 + ((colhalf * 2) ^ ((r & 7) << 4)));
}

static __device__ __forceinline__ uint32_t smem_u32(const void* p) {
    uint32_t a;
    asm("{ .reg .u64 t; cvta.to.shared.u64 t, %1; cvt.u32.u64 %0, t; }" : "=r"(a) : "l"(p));
    return a;
}

// ---------------- cp.async ----------------
static __device__ __forceinline__ void cp_async16(uint32_t dst, const void* src, uint32_t srcsize) {
    asm volatile("cp.async.cg.shared.global [%0], [%1], 16, %2;"
                 :: "r"(dst), "l"(src), "r"(srcsize) : "memory");
}
static __device__ __forceinline__ void cp_commit() {
    asm volatile("cp.async.commit_group;" ::: "memory");
}
static __device__ __forceinline__ void cp_wait0() {
    asm volatile("cp.async.wait_group 0;" ::: "memory");
}

// ---------------- mma / ldmatrix wrappers ----------------
static __device__ __forceinline__ void ldsm4(uint32_t* r, uint32_t a) {
    asm volatile("ldmatrix.sync.aligned.m8n8.x4.shared.b16 {%0,%1,%2,%3}, [%4];"
                 : "=r"(r[0]), "=r"(r[1]), "=r"(r[2]), "=r"(r[3]) : "r"(a));
}
static __device__ __forceinline__ void ldsm4t(uint32_t* r, uint32_t a) {
    asm volatile("ldmatrix.sync.aligned.m8n8.x4.trans.shared.b16 {%0,%1,%2,%3}, [%4];"
                 : "=r"(r[0]), "=r"(r[1]), "=r"(r[2]), "=r"(r[3]) : "r"(a));
}
static __device__ __forceinline__ void mma16816(float* d, const uint32_t* a, const uint32_t* b) {
    asm volatile("mma.sync.aligned.m16n8k16.row.col.f32.f16.f16.f32 "
                 "{%0,%1,%2,%3}, {%4,%5,%6,%7}, {%8,%9}, {%0,%1,%2,%3};"
                 : "+f"(d[0]), "+f"(d[1]), "+f"(d[2]), "+f"(d[3])
                 : "r"(a[0]), "r"(a[1]), "r"(a[2]), "r"(a[3]), "r"(b[0]), "r"(b[1]));
}
static __device__ __forceinline__ uint32_t packh2(half a, half b) {
    half2 h = __halves2half2(a, b);
    return *reinterpret_cast<uint32_t*>(&h);
}

// issue cp.async loads for one X tile into the stage buffer
static __device__ __forceinline__ void stage_tile(const float* __restrict__ data,
                                                  int N, int tile, uint32_t sb, int t) {
    const int base = tile * 128;
    #pragma unroll
    for (int k = 0; k < 8; k++) {
        int c = t + k * THREADS;          // 16B chunk id, 0..2047
        int row = c >> 4;
        int grow = base + row;
        const float* src = data + (size_t)grow * 64 + (c & 15) * 4;
        uint32_t ok = (grow < N) ? 16u : 0u;
        cp_async16(sb + OFF_STAGE + c * 16, src, ok);
    }
    cp_commit();
}

// ---------------- fused pass ----------------
__global__ void __launch_bounds__(THREADS, 2)
fcm_pass_mma(const float* __restrict__ data, const float* __restrict__ u0,
             int N, int pp, int mode)
{
    extern __shared__ char smem[];
    const uint32_t sb = smem_u32(smem);
    float* x2s = (float*)(smem + OFF_X2);
    float* c2s = (float*)(smem + OFF_C2);

    const int t = threadIdx.x;
    const int w = t >> 5, lane = t & 31;
    const int quad = lane >> 2, qid = lane & 3;
    const int seg = lane >> 3, q = lane & 7;
    const int bucket = blockIdx.x & (NBUCKET - 1);

    // C hi tile + exact c2 (mode 1 only)
    if (mode) {
        const float* C = g_C[pp];
        for (int i = t; i < 4096; i += THREADS) {
            int j = i >> 6, d = i & 63;
            *(half*)(smem + OFF_CH + swz(j, d)) = __float2half_rn(C[i]);
        }
        if (t < 64) {
            const float* Cr = g_C[pp] + t * 64;
            float s = 0.f;
            #pragma unroll 8
            for (int d = 0; d < 64; d++) s += Cr[d] * Cr[d];
            c2s[t] = s;
        }
    }

    float G[4][4];
    #pragma unroll
    for (int a = 0; a < 4; a++)
        #pragma unroll
        for (int b = 0; b < 4; b++) G[a][b] = 0.f;
    float DEN[4] = {0.f, 0.f, 0.f, 0.f};

    const int ntiles = (N + 127) >> 7;
    const int jm = (w & 3) * 16;        // GEMM2 m-tile (j rows)
    const int nb = (w >> 2) * 4;        // GEMM2 n-tile base (d/8)

    // prologue: stage first tile
    if (blockIdx.x < ntiles) stage_tile(data, N, blockIdx.x, sb, t);

    for (int tile = blockIdx.x; tile < ntiles; tile += gridDim.x) {
        cp_wait0();
        __syncthreads();   // stage(t) visible; GEMM2(t-1) reads of X/U done; C setup done

        // ---- convert stage fp32 -> swizzled fp16 hi/lo + exact fp32 row norms ----
        #pragma unroll
        for (int it = 0; it < 4; it++) {
            int i = t + it * THREADS;          // 0..1023
            int r = i >> 3, c = i & 7;         // row, 8-float chunk
            float4 v0 = *reinterpret_cast<const float4*>(smem + OFF_STAGE + r * 256 + c * 32);
            float4 v1 = *reinterpret_cast<const float4*>(smem + OFF_STAGE + r * 256 + c * 32 + 16);
            float f[8] = {v0.x, v0.y, v0.z, v0.w, v1.x, v1.y, v1.z, v1.w};
            uint32_t hp[4], lp[4];
            #pragma unroll
            for (int k = 0; k < 4; k++) {
                half h0 = __float2half_rn(f[2*k]),   h1 = __float2half_rn(f[2*k+1]);
                half l0 = __float2half_rn(f[2*k]   - __half2float(h0));
                half l1 = __float2half_rn(f[2*k+1] - __half2float(h1));
                hp[k] = packh2(h0, h1);
                lp[k] = packh2(l0, l1);
            }
            uint32_t off = swz(r, c * 8);
            *reinterpret_cast<uint4*>(smem + OFF_XH + off) = make_uint4(hp[0], hp[1], hp[2], hp[3]);
            *reinterpret_cast<uint4*>(smem + OFF_XL + off) = make_uint4(lp[0], lp[1], lp[2], lp[3]);
            float sq = 0.f;
            #pragma unroll
            for (int k = 0; k < 8; k++) sq += f[k] * f[k];
            sq += __shfl_xor_sync(0xFFFFFFFFu, sq, 1);
            sq += __shfl_xor_sync(0xFFFFFFFFu, sq, 2);
            sq += __shfl_xor_sync(0xFFFFFFFFu, sq, 4);
            if (c == 0) x2s[r] = sq;
        }
        __syncthreads();   // X tiles + x2 ready; all stage reads complete

        // stage next tile (overlaps GEMM1 + epilogue + GEMM2)
        int ntile = tile + gridDim.x;
        if (ntile < ntiles) stage_tile(data, N, ntile, sb, t);

        // ---- memberships ----
        float S[8][4];
        const int r1l = 16 * w + quad;     // local rows this thread owns
        const int grow1 = tile * 128 + r1l;
        const int grow2 = grow1 + 8;

        if (mode) {
            #pragma unroll
            for (int tn = 0; tn < 8; tn++)
                #pragma unroll
                for (int b = 0; b < 4; b++) S[tn][b] = 0.f;
            // GEMM1 single chain: S = Xh.Ch^T   (warp w: rows 16w..16w+15)
            #pragma unroll
            for (int kk = 0; kk < 4; kk++) {
                uint32_t ah[4];
                ldsm4(ah, sb + OFF_XH + swz(16 * w + (seg & 1) * 8 + q,
                                            kk * 16 + (seg >> 1) * 8));
                #pragma unroll
                for (int tnp = 0; tnp < 4; tnp++) {
                    uint32_t bb[4];
                    ldsm4(bb, sb + OFF_CH + swz(16 * tnp + ((lane >> 4) << 3) + q,
                                                kk * 16 + ((lane >> 3) & 1) * 8));
                    mma16816(S[2 * tnp],     ah, bb);
                    mma16816(S[2 * tnp + 1], ah, bb + 2);
                }
            }
            // S -> w = 1/max(x2+c2-2S, 0)
            float xx1 = x2s[r1l], xx2 = x2s[r1l + 8];
            #pragma unroll
            for (int tn = 0; tn < 8; tn++) {
                int j = 8 * tn + qid * 2;
                float ca = c2s[j], cb = c2s[j + 1];
                S[tn][0] = 1.f / fmaxf(xx1 + ca - 2.f * S[tn][0], 0.f);
                S[tn][1] = 1.f / fmaxf(xx1 + cb - 2.f * S[tn][1], 0.f);
                S[tn][2] = 1.f / fmaxf(xx2 + ca - 2.f * S[tn][2], 0.f);
                S[tn][3] = 1.f / fmaxf(xx2 + cb - 2.f * S[tn][3], 0.f);
            }
        } else {
            // initial U from u0_raw
            #pragma unroll
            for (int tn = 0; tn < 8; tn++) {
                int j = 8 * tn + qid * 2;
                float2 p1 = make_float2(0.f, 0.f), p2 = p1;
                if (grow1 < N) p1 = *reinterpret_cast<const float2*>(u0 + (size_t)grow1 * 64 + j);
                if (grow2 < N) p2 = *reinterpret_cast<const float2*>(u0 + (size_t)grow2 * 64 + j);
                S[tn][0] = p1.x; S[tn][1] = p1.y; S[tn][2] = p2.x; S[tn][3] = p2.y;
            }
        }

        // row sums across the 4-lane quad
        float s1 = 0.f, s2 = 0.f;
        #pragma unroll
        for (int tn = 0; tn < 8; tn++) { s1 += S[tn][0] + S[tn][1]; s2 += S[tn][2] + S[tn][3]; }
        s1 += __shfl_xor_sync(0xFFFFFFFFu, s1, 1);
        s1 += __shfl_xor_sync(0xFFFFFFFFu, s1, 2);
        s2 += __shfl_xor_sync(0xFFFFFFFFu, s2, 1);
        s2 += __shfl_xor_sync(0xFFFFFFFFu, s2, 2);
        float i1 = (grow1 < N) ? 1.f / s1 : 0.f;
        float i2 = (grow2 < N) ? 1.f / s2 : 0.f;

        // u^2 -> fp16 hi/lo -> smem U tiles
        #pragma unroll
        for (int tn = 0; tn < 8; tn++) {
            int j = 8 * tn + qid * 2;
            float ua0 = S[tn][0] * i1; ua0 *= ua0;
            float ua1 = S[tn][1] * i1; ua1 *= ua1;
            float ub0 = S[tn][2] * i2; ub0 *= ub0;
            float ub1 = S[tn][3] * i2; ub1 *= ub1;
            half ha0 = __float2half_rn(ua0), ha1 = __float2half_rn(ua1);
            half hb0 = __float2half_rn(ub0), hb1 = __float2half_rn(ub1);
            half la0 = __float2half_rn(ua0 - __half2float(ha0));
            half la1 = __float2half_rn(ua1 - __half2float(ha1));
            half lb0 = __float2half_rn(ub0 - __half2float(hb0));
            half lb1 = __float2half_rn(ub1 - __half2float(hb1));
            uint32_t o1 = swz(r1l, j), o2 = swz(r1l + 8, j);
            *(uint32_t*)(smem + OFF_UH + o1) = packh2(ha0, ha1);
            *(uint32_t*)(smem + OFF_UL + o1) = packh2(la0, la1);
            *(uint32_t*)(smem + OFF_UH + o2) = packh2(hb0, hb1);
            *(uint32_t*)(smem + OFF_UL + o2) = packh2(lb0, lb1);
        }
        __syncthreads();   // U visible

        // ---- GEMM2: G[j][d] += U^T X (3 chains); den += Uh^T ones (1 chain) ----
        {
            const uint32_t ones[2] = {0x3C003C00u, 0x3C003C00u};
            #pragma unroll
            for (int rr = 0; rr < 8; rr++) {
                int ur = rr * 16 + (seg >> 1) * 8 + q;
                int uc = jm + (seg & 1) * 8;
                uint32_t uoff = sb + swz(ur, uc);
                uint32_t auh[4], aul[4];
                ldsm4t(auh, uoff + OFF_UH);
                ldsm4t(aul, uoff + OFF_UL);
                #pragma unroll
                for (int tnp = 0; tnp < 2; tnp++) {
                    int d0 = 8 * (nb + 2 * tnp);
                    uint32_t xoff = swz(rr * 16 + ((lane >> 3) & 1) * 8 + q,
                                        d0 + (lane >> 4) * 8);
                    uint32_t bxh[4], bxl[4];
                    ldsm4t(bxh, sb + OFF_XH + xoff);
                    ldsm4t(bxl, sb + OFF_XL + xoff);
                    mma16816(G[2 * tnp],     auh, bxh);
                    mma16816(G[2 * tnp],     auh, bxl);
                    mma16816(G[2 * tnp],     aul, bxh);
                    mma16816(G[2 * tnp + 1], auh, bxh + 2);
                    mma16816(G[2 * tnp + 1], auh, bxl + 2);
                    mma16816(G[2 * tnp + 1], aul, bxh + 2);
                }
                if (w < 4) mma16816(DEN, auh, ones);
            }
        }
    }

    // ---- flush block partials (bucketed atomics) ----
    {
        int j1 = jm + quad;
        #pragma unroll
        for (int tn = 0; tn < 4; tn++) {
            int d = 8 * (nb + tn) + qid * 2;
            atomicAdd(&g_part[bucket][j1 * 64 + d],           G[tn][0]);
            atomicAdd(&g_part[bucket][j1 * 64 + d + 1],       G[tn][1]);
            atomicAdd(&g_part[bucket][(j1 + 8) * 64 + d],     G[tn][2]);
            atomicAdd(&g_part[bucket][(j1 + 8) * 64 + d + 1], G[tn][3]);
        }
        if (w < 4 && qid == 0) {
            atomicAdd(&g_denp[bucket][j1],     DEN[0]);
            atomicAdd(&g_denp[bucket][j1 + 8], DEN[2]);
        }
    }
}

// ---------------- tiny kernels ----------------
__global__ void fcm_zero() {
    int t = threadIdx.x;
    for (int b = 0; b < NBUCKET; b++) {
        for (int i = t; i < 4096; i += THREADS) g_part[b][i] = 0.f;
        if (t < 64) g_denp[b][t] = 0.f;
    }
    if (t == 0) g_done = 0;
}

__global__ void fcm_center(float* __restrict__ out, int pnew, int do_diff) {
    __shared__ float red[THREADS];
    __shared__ float denS[64];
    const int t = threadIdx.x;
    const int done = g_done;
    if (t < 64) {
        float s = 0.f;
        #pragma unroll
        for (int b = 0; b < NBUCKET; b++) { s += g_denp[b][t]; g_denp[b][t] = 0.f; }
        denS[t] = s;
    }
    __syncthreads();
    float local = 0.f;
    float* Cn = g_C[pnew];
    const float* Cp = g_C[pnew ^ 1];
    for (int i = t; i < 4096; i += THREADS) {
        float num = 0.f;
        #pragma unroll
        for (int b = 0; b < NBUCKET; b++) { num += g_part[b][i]; g_part[b][i] = 0.f; }
        float c = num / denS[i >> 6];
        Cn[i] = c;
        if (do_diff) {
            float p = Cp[i];
            float dd = c - p;
            local += dd * dd;
            if (!done) out[i] = p;   // out tracks C_{k-1}; frozen once done
        }
    }
    if (do_diff) {
        red[t] = local;
        __syncthreads();
        #pragma unroll
        for (int s = 128; s > 0; s >>= 1) {
            if (t < s) red[t] += red[t + s];
            __syncthreads();
        }
        if (t == 0 && !done && sqrtf(red[0]) < 1e-8f) g_done = 1;
    }
}

__global__ void fcm_final(float* __restrict__ out, int plast) {
    if (g_done) return;
    const int t = threadIdx.x;
    for (int i = t; i < 4096; i += THREADS) out[i] = g_C[plast][i];
}

// ---------------- host launch ----------------
extern "C" void kernel_launch(void* const* d_in, const int* in_sizes, int n_in,
                              void* d_out, int out_size) {
    const float* data = (const float*)d_in[0];
    const float* u0   = (const float*)d_in[1];
    const int N = in_sizes[0] / 64;     // 300000
    float* out = (float*)d_out;

    cudaFuncSetAttribute(fcm_pass_mma, cudaFuncAttributeMaxDynamicSharedMemorySize, SMEM_BYTES);

    fcm_zero<<<1, THREADS>>>();
    // C_0 = center(U_0) from u0_raw
    fcm_pass_mma<<<GRIDSZ, THREADS, SMEM_BYTES>>>(data, u0, N, 0, 0);
    fcm_center<<<1, THREADS>>>(out, 0, 0);
    // 25 iterations with convergence latch on ||C_i - C_{i-1}||_F
    for (int i = 1; i <= 25; i++) {
        fcm_pass_mma<<<GRIDSZ, THREADS, SMEM_BYTES>>>(data, u0, N, (i - 1) & 1, 1);
        fcm_center<<<1, THREADS>>>(out, i & 1, 1);
    }
    fcm_final<<<1, THREADS>>>(out, 1);
}

// round 6
// speedup vs baseline: 3.6929x; 1.2955x over previous
#include <cuda_runtime.h>
#include <cuda_fp16.h>
#include <cstdint>

#define THREADS 256
#define NBUCKET 16

// ---------------- device-global state (no allocations allowed) ----------------
__device__ float g_C[2][64 * 64];
__device__ float g_part[NBUCKET][64 * 64];
__device__ float g_denp[NBUCKET][64];
__device__ float g_diff;
__device__ int   g_done;
__device__ unsigned g_bar_cnt;
__device__ volatile unsigned g_bar_gen;

// ---------------- smem layout (bytes) ----------------
#define OFF_XH    0        // [128][64] half, swizzled, 16 KB
#define OFF_XL    16384
#define OFF_UH    32768    // [128 r][64 j] half, swizzled, 16 KB
#define OFF_UL    49152
#define OFF_CH    65536    // [64][64] half, 8 KB
#define OFF_STAGE 73728    // [128][64] fp32 raw staging, 32 KB
#define OFF_X2    106496   // float[128]
#define OFF_C2    107008   // float[64]
#define SMEM_BYTES 107264

// XOR swizzle: 16B-chunk permutation within a 128B row (conflict-free ldmatrix)
static __device__ __forceinline__ uint32_t swz(int r, int colhalf) {
    return (uint32_t)(r * 128 + ((colhalf * 2) ^ ((r & 7) << 4)));
}
static __device__ __forceinline__ uint32_t smem_u32(const void* p) {
    uint32_t a;
    asm("{ .reg .u64 t; cvta.to.shared.u64 t, %1; cvt.u32.u64 %0, t; }" : "=r"(a) : "l"(p));
    return a;
}
static __device__ __forceinline__ float frcp(float x) {
    float y;
    asm("rcp.approx.f32 %0, %1;" : "=f"(y) : "f"(x));
    return y;
}

// ---------------- cp.async ----------------
static __device__ __forceinline__ void cp_async16(uint32_t dst, const void* src, uint32_t srcsize) {
    asm volatile("cp.async.cg.shared.global [%0], [%1], 16, %2;"
                 :: "r"(dst), "l"(src), "r"(srcsize) : "memory");
}
static __device__ __forceinline__ void cp_commit() {
    asm volatile("cp.async.commit_group;" ::: "memory");
}
static __device__ __forceinline__ void cp_wait0() {
    asm volatile("cp.async.wait_group 0;" ::: "memory");
}

// ---------------- mma / ldmatrix wrappers ----------------
static __device__ __forceinline__ void ldsm4(uint32_t* r, uint32_t a) {
    asm volatile("ldmatrix.sync.aligned.m8n8.x4.shared.b16 {%0,%1,%2,%3}, [%4];"
                 : "=r"(r[0]), "=r"(r[1]), "=r"(r[2]), "=r"(r[3]) : "r"(a));
}
static __device__ __forceinline__ void ldsm4t(uint32_t* r, uint32_t a) {
    asm volatile("ldmatrix.sync.aligned.m8n8.x4.trans.shared.b16 {%0,%1,%2,%3}, [%4];"
                 : "=r"(r[0]), "=r"(r[1]), "=r"(r[2]), "=r"(r[3]) : "r"(a));
}
static __device__ __forceinline__ void mma16816(float* d, const uint32_t* a, const uint32_t* b) {
    asm volatile("mma.sync.aligned.m16n8k16.row.col.f32.f16.f16.f32 "
                 "{%0,%1,%2,%3}, {%4,%5,%6,%7}, {%8,%9}, {%0,%1,%2,%3};"
                 : "+f"(d[0]), "+f"(d[1]), "+f"(d[2]), "+f"(d[3])
                 : "r"(a[0]), "r"(a[1]), "r"(a[2]), "r"(a[3]), "r"(b[0]), "r"(b[1]));
}
static __device__ __forceinline__ uint32_t packh2(half a, half b) {
    half2 h = __halves2half2(a, b);
    return *reinterpret_cast<uint32_t*>(&h);
}

// issue cp.async loads for one X tile into the stage buffer
static __device__ __forceinline__ void stage_tile(const float* __restrict__ data,
                                                  int N, int tile, uint32_t sb, int t) {
    const int base = tile * 128;
    #pragma unroll
    for (int k = 0; k < 8; k++) {
        int c = t + k * THREADS;          // 16B chunk id, 0..2047
        int row = c >> 4;
        int grow = base + row;
        const float* src = data + (size_t)grow * 64 + (c & 15) * 4;
        uint32_t ok = (grow < N) ? 16u : 0u;
        cp_async16(sb + OFF_STAGE + c * 16, src, ok);
    }
    cp_commit();
}

// software grid barrier (all CTAs must be co-resident; grid sized by occupancy)
static __device__ __forceinline__ void gridbar(int nblk) {
    __syncthreads();
    if (threadIdx.x == 0) {
        unsigned gen = g_bar_gen;
        __threadfence();
        if (atomicAdd(&g_bar_cnt, 1u) == (unsigned)nblk - 1u) {
            g_bar_cnt = 0;
            __threadfence();
            g_bar_gen = gen + 1u;
        } else {
            while (g_bar_gen == gen) { __nanosleep(64); }
        }
    }
    __syncthreads();
}

// ---------------- persistent fused kernel: all 26 iterations ----------------
__global__ void __launch_bounds__(THREADS, 2)
fcm_persist(const float* __restrict__ data, const float* __restrict__ u0,
            int N, float* __restrict__ out)
{
    extern __shared__ char smem[];
    const uint32_t sb = smem_u32(smem);
    float* x2s = (float*)(smem + OFF_X2);
    float* c2s = (float*)(smem + OFF_C2);

    const int t = threadIdx.x;
    const int w = t >> 5, lane = t & 31;
    const int quad = lane >> 2, qid = lane & 3;
    const int seg = lane >> 3, q = lane & 7;
    const int bucket = blockIdx.x & (NBUCKET - 1);
    const int nblk = gridDim.x;
    const int ntiles = (N + 127) >> 7;
    const int jm = (w & 3) * 16;        // GEMM2 m-tile (j rows)
    const int nb = (w >> 2) * 4;        // GEMM2 n-tile base (d/8)

    if (blockIdx.x == 0 && t == 0) g_done = 0;

    for (int iter = 0; iter <= 25; iter++) {
        const int mode = (iter > 0);

        float G[4][4];
        #pragma unroll
        for (int a = 0; a < 4; a++)
            #pragma unroll
            for (int b = 0; b < 4; b++) G[a][b] = 0.f;
        float DEN[4] = {0.f, 0.f, 0.f, 0.f};

        // prologue: stage first tile
        if (blockIdx.x < ntiles) stage_tile(data, N, blockIdx.x, sb, t);

        for (int tile = blockIdx.x; tile < ntiles; tile += nblk) {
            cp_wait0();
            __syncthreads();   // stage(t) visible; GEMM2(t-1) reads done; C tile ready

            // ---- convert stage fp32 -> swizzled fp16 hi/lo + exact fp32 row norms ----
            #pragma unroll
            for (int it = 0; it < 4; it++) {
                int i = t + it * THREADS;
                int r = i >> 3, c = i & 7;
                float4 v0 = *reinterpret_cast<const float4*>(smem + OFF_STAGE + r * 256 + c * 32);
                float4 v1 = *reinterpret_cast<const float4*>(smem + OFF_STAGE + r * 256 + c * 32 + 16);
                float f[8] = {v0.x, v0.y, v0.z, v0.w, v1.x, v1.y, v1.z, v1.w};
                uint32_t hp[4], lp[4];
                #pragma unroll
                for (int k = 0; k < 4; k++) {
                    half h0 = __float2half_rn(f[2*k]),   h1 = __float2half_rn(f[2*k+1]);
                    half l0 = __float2half_rn(f[2*k]   - __half2float(h0));
                    half l1 = __float2half_rn(f[2*k+1] - __half2float(h1));
                    hp[k] = packh2(h0, h1);
                    lp[k] = packh2(l0, l1);
                }
                uint32_t off = swz(r, c * 8);
                *reinterpret_cast<uint4*>(smem + OFF_XH + off) = make_uint4(hp[0], hp[1], hp[2], hp[3]);
                *reinterpret_cast<uint4*>(smem + OFF_XL + off) = make_uint4(lp[0], lp[1], lp[2], lp[3]);
                float sq = 0.f;
                #pragma unroll
                for (int k = 0; k < 8; k++) sq += f[k] * f[k];
                sq += __shfl_xor_sync(0xFFFFFFFFu, sq, 1);
                sq += __shfl_xor_sync(0xFFFFFFFFu, sq, 2);
                sq += __shfl_xor_sync(0xFFFFFFFFu, sq, 4);
                if (c == 0) x2s[r] = sq;
            }
            __syncthreads();

            // stage next tile (overlaps GEMM1 + epilogue + GEMM2)
            int ntile = tile + nblk;
            if (ntile < ntiles) stage_tile(data, N, ntile, sb, t);

            // ---- memberships ----
            float S[8][4];
            const int r1l = 16 * w + quad;
            const int grow1 = tile * 128 + r1l;
            const int grow2 = grow1 + 8;

            if (mode) {
                #pragma unroll
                for (int tn = 0; tn < 8; tn++)
                    #pragma unroll
                    for (int b = 0; b < 4; b++) S[tn][b] = 0.f;
                #pragma unroll
                for (int kk = 0; kk < 4; kk++) {
                    uint32_t ah[4];
                    ldsm4(ah, sb + OFF_XH + swz(16 * w + (seg & 1) * 8 + q,
                                                kk * 16 + (seg >> 1) * 8));
                    #pragma unroll
                    for (int tnp = 0; tnp < 4; tnp++) {
                        uint32_t bb[4];
                        ldsm4(bb, sb + OFF_CH + swz(16 * tnp + ((lane >> 4) << 3) + q,
                                                    kk * 16 + ((lane >> 3) & 1) * 8));
                        mma16816(S[2 * tnp],     ah, bb);
                        mma16816(S[2 * tnp + 1], ah, bb + 2);
                    }
                }
                float xx1 = x2s[r1l], xx2 = x2s[r1l + 8];
                #pragma unroll
                for (int tn = 0; tn < 8; tn++) {
                    int j = 8 * tn + qid * 2;
                    float ca = c2s[j], cb = c2s[j + 1];
                    S[tn][0] = frcp(fmaxf(xx1 + ca - 2.f * S[tn][0], 0.f));
                    S[tn][1] = frcp(fmaxf(xx1 + cb - 2.f * S[tn][1], 0.f));
                    S[tn][2] = frcp(fmaxf(xx2 + ca - 2.f * S[tn][2], 0.f));
                    S[tn][3] = frcp(fmaxf(xx2 + cb - 2.f * S[tn][3], 0.f));
                }
            } else {
                #pragma unroll
                for (int tn = 0; tn < 8; tn++) {
                    int j = 8 * tn + qid * 2;
                    float2 p1 = make_float2(0.f, 0.f), p2 = p1;
                    if (grow1 < N) p1 = *reinterpret_cast<const float2*>(u0 + (size_t)grow1 * 64 + j);
                    if (grow2 < N) p2 = *reinterpret_cast<const float2*>(u0 + (size_t)grow2 * 64 + j);
                    S[tn][0] = p1.x; S[tn][1] = p1.y; S[tn][2] = p2.x; S[tn][3] = p2.y;
                }
            }

            float s1 = 0.f, s2 = 0.f;
            #pragma unroll
            for (int tn = 0; tn < 8; tn++) { s1 += S[tn][0] + S[tn][1]; s2 += S[tn][2] + S[tn][3]; }
            s1 += __shfl_xor_sync(0xFFFFFFFFu, s1, 1);
            s1 += __shfl_xor_sync(0xFFFFFFFFu, s1, 2);
            s2 += __shfl_xor_sync(0xFFFFFFFFu, s2, 1);
            s2 += __shfl_xor_sync(0xFFFFFFFFu, s2, 2);
            float i1 = (grow1 < N) ? frcp(s1) : 0.f;
            float i2 = (grow2 < N) ? frcp(s2) : 0.f;

            #pragma unroll
            for (int tn = 0; tn < 8; tn++) {
                int j = 8 * tn + qid * 2;
                float ua0 = S[tn][0] * i1; ua0 *= ua0;
                float ua1 = S[tn][1] * i1; ua1 *= ua1;
                float ub0 = S[tn][2] * i2; ub0 *= ub0;
                float ub1 = S[tn][3] * i2; ub1 *= ub1;
                half ha0 = __float2half_rn(ua0), ha1 = __float2half_rn(ua1);
                half hb0 = __float2half_rn(ub0), hb1 = __float2half_rn(ub1);
                half la0 = __float2half_rn(ua0 - __half2float(ha0));
                half la1 = __float2half_rn(ua1 - __half2float(ha1));
                half lb0 = __float2half_rn(ub0 - __half2float(hb0));
                half lb1 = __float2half_rn(ub1 - __half2float(hb1));
                uint32_t o1 = swz(r1l, j), o2 = swz(r1l + 8, j);
                *(uint32_t*)(smem + OFF_UH + o1) = packh2(ha0, ha1);
                *(uint32_t*)(smem + OFF_UL + o1) = packh2(la0, la1);
                *(uint32_t*)(smem + OFF_UH + o2) = packh2(hb0, hb1);
                *(uint32_t*)(smem + OFF_UL + o2) = packh2(lb0, lb1);
            }
            __syncthreads();

            // ---- GEMM2: G += U^T X (3 chains); den += Uh^T ones ----
            {
                const uint32_t ones[2] = {0x3C003C00u, 0x3C003C00u};
                #pragma unroll
                for (int rr = 0; rr < 8; rr++) {
                    int ur = rr * 16 + (seg >> 1) * 8 + q;
                    int uc = jm + (seg & 1) * 8;
                    uint32_t uoff = sb + swz(ur, uc);
                    uint32_t auh[4], aul[4];
                    ldsm4t(auh, uoff + OFF_UH);
                    ldsm4t(aul, uoff + OFF_UL);
                    #pragma unroll
                    for (int tnp = 0; tnp < 2; tnp++) {
                        int d0 = 8 * (nb + 2 * tnp);
                        uint32_t xoff = swz(rr * 16 + ((lane >> 3) & 1) * 8 + q,
                                            d0 + (lane >> 4) * 8);
                        uint32_t bxh[4], bxl[4];
                        ldsm4t(bxh, sb + OFF_XH + xoff);
                        ldsm4t(bxl, sb + OFF_XL + xoff);
                        mma16816(G[2 * tnp],     auh, bxh);
                        mma16816(G[2 * tnp],     auh, bxl);
                        mma16816(G[2 * tnp],     aul, bxh);
                        mma16816(G[2 * tnp + 1], auh, bxh + 2);
                        mma16816(G[2 * tnp + 1], auh, bxl + 2);
                        mma16816(G[2 * tnp + 1], aul, bxh + 2);
                    }
                    if (w < 4) mma16816(DEN, auh, ones);
                }
            }
        }

        // ---- flush block partials (bucketed atomics) ----
        {
            int j1 = jm + quad;
            #pragma unroll
            for (int tn = 0; tn < 4; tn++) {
                int d = 8 * (nb + tn) + qid * 2;
                atomicAdd(&g_part[bucket][j1 * 64 + d],           G[tn][0]);
                atomicAdd(&g_part[bucket][j1 * 64 + d + 1],       G[tn][1]);
                atomicAdd(&g_part[bucket][(j1 + 8) * 64 + d],     G[tn][2]);
                atomicAdd(&g_part[bucket][(j1 + 8) * 64 + d + 1], G[tn][3]);
            }
            if (w < 4 && qid == 0) {
                atomicAdd(&g_denp[bucket][j1],     DEN[0]);
                atomicAdd(&g_denp[bucket][j1 + 8], DEN[2]);
            }
        }

        gridbar(nblk);

        // ---- distributed center: block j computes cluster row j ----
        const int pnew = iter & 1, pold = pnew ^ 1;
        if (blockIdx.x < 64 && t < 64) {
            const int j = blockIdx.x, d = t;
            float num = 0.f, den = 0.f;
            #pragma unroll
            for (int b = 0; b < NBUCKET; b++) {
                num += g_part[b][j * 64 + d];
                g_part[b][j * 64 + d] = 0.f;
                den += g_denp[b][j];
            }
            if (t < NBUCKET) g_denp[t][j] = 0.f;
            float c = num / den;
            g_C[pnew][j * 64 + d] = c;
            if (iter > 0) {
                float dd = c - g_C[pold][j * 64 + d];
                float s = dd * dd;
                #pragma unroll
                for (int m = 16; m > 0; m >>= 1) s += __shfl_xor_sync(0xFFFFFFFFu, s, m);
                if ((t & 31) == 0) atomicAdd(&g_diff, s);
            }
        }

        gridbar(nblk);

        // ---- convergence latch (block 0 only; out tracks C_{k-1}, frozen once done) ----
        if (blockIdx.x == 0 && iter > 0) {
            int done = g_done;
            __syncthreads();
            if (!done)
                for (int i = t; i < 4096; i += THREADS) out[i] = g_C[pold][i];
            __syncthreads();
            if (t == 0) {
                float df = g_diff;
                if (!done && sqrtf(df) < 1e-8f) g_done = 1;
                g_diff = 0.f;
            }
        }

        // ---- build C tile for next pass ----
        if (iter < 25) {
            const float* C = g_C[pnew];
            for (int i = t; i < 4096; i += THREADS) {
                int j = i >> 6, d = i & 63;
                *(half*)(smem + OFF_CH + swz(j, d)) = __float2half_rn(C[i]);
            }
            if (t < 64) {
                const float* Cr = C + t * 64;
                float s = 0.f;
                #pragma unroll 8
                for (int d = 0; d < 64; d++) s += Cr[d] * Cr[d];
                c2s[t] = s;
            }
            __syncthreads();
        }
    }

    // ---- final: if never converged, answer is C_25 ----
    if (blockIdx.x == 0) {
        __syncthreads();
        if (!g_done)
            for (int i = t; i < 4096; i += THREADS) out[i] = g_C[1][i];
    }
}

// ---------------- host launch ----------------
extern "C" void kernel_launch(void* const* d_in, const int* in_sizes, int n_in,
                              void* d_out, int out_size) {
    const float* data = (const float*)d_in[0];
    const float* u0   = (const float*)d_in[1];
    const int N = in_sizes[0] / 64;     // 300000
    float* out = (float*)d_out;

    cudaFuncSetAttribute(fcm_persist, cudaFuncAttributeMaxDynamicSharedMemorySize, SMEM_BYTES);

    int nbsm = 0;
    cudaOccupancyMaxActiveBlocksPerMultiprocessor(&nbsm, fcm_persist, THREADS, SMEM_BYTES);
    if (nbsm < 1) nbsm = 1;
    if (nbsm > 2) nbsm = 2;
    int dev = 0, nsm = 148;
    cudaGetDevice(&dev);
    cudaDeviceGetAttribute(&nsm, cudaDevAttrMultiProcessorCount, dev);
    int grid = nbsm * nsm;   // all CTAs co-resident -> software grid barrier is safe

    fcm_persist<<<grid, THREADS, SMEM_BYTES>>>(data, u0, N, out);
}

// round 7
// speedup vs baseline: 4.2040x; 1.1384x over previous
#include <cuda_runtime.h>
#include <cuda_fp16.h>
#include <cstdint>

#define THREADS 256
#define NBUCKET 16
#define MAXTILES 2350   // >= ceil(300000/128)

// ---------------- device-global state (no allocations allowed) ----------------
__device__ float g_C[2][64 * 64];
__device__ float g_part[NBUCKET][64 * 64];
__device__ float g_denp[NBUCKET][64];
__device__ float g_diff;
__device__ int   g_done;
__device__ unsigned g_bar_cnt;
__device__ volatile unsigned g_bar_gen;

// precomputed fp16 split of X, per-tile swizzled smem images (16 KB each)
__device__ char  gXh[(size_t)MAXTILES * 16384];
__device__ char  gXl[(size_t)MAXTILES * 16384];
__device__ float gx2[(size_t)MAXTILES * 128];

// ---------------- smem layout (bytes) ----------------
#define OFF_XH0   0        // X hi buf0 [128][64] half swizzled, 16 KB
#define OFF_XL0   16384
#define OFF_XH1   32768
#define OFF_XL1   49152
#define OFF_UH    65536    // U^2 hi [128 r][64 j] half swizzled, 16 KB
#define OFF_UL    81920
#define OFF_CH    98304    // C hi [64][64] half swizzled, 8 KB
#define OFF_X2    106496   // float[2][128]
#define OFF_C2    107520   // float[64]
#define SMEM_BYTES 107776

// XOR swizzle: 16B-chunk permutation within a 128B row (conflict-free ldmatrix)
static __device__ __forceinline__ uint32_t swz(int r, int colhalf) {
    return (uint32_t)(r * 128 + ((colhalf * 2) ^ ((r & 7) << 4)));
}
static __device__ __forceinline__ uint32_t smem_u32(const void* p) {
    uint32_t a;
    asm("{ .reg .u64 t; cvta.to.shared.u64 t, %1; cvt.u32.u64 %0, t; }" : "=r"(a) : "l"(p));
    return a;
}
static __device__ __forceinline__ float frcp(float x) {
    float y;
    asm("rcp.approx.f32 %0, %1;" : "=f"(y) : "f"(x));
    return y;
}

// ---------------- cp.async ----------------
static __device__ __forceinline__ void cp_async16(uint32_t dst, const void* src) {
    asm volatile("cp.async.cg.shared.global [%0], [%1], 16;"
                 :: "r"(dst), "l"(src) : "memory");
}
static __device__ __forceinline__ void cp_commit() {
    asm volatile("cp.async.commit_group;" ::: "memory");
}
static __device__ __forceinline__ void cp_wait0() {
    asm volatile("cp.async.wait_group 0;" ::: "memory");
}

// ---------------- mma / ldmatrix wrappers ----------------
static __device__ __forceinline__ void ldsm4(uint32_t* r, uint32_t a) {
    asm volatile("ldmatrix.sync.aligned.m8n8.x4.shared.b16 {%0,%1,%2,%3}, [%4];"
                 : "=r"(r[0]), "=r"(r[1]), "=r"(r[2]), "=r"(r[3]) : "r"(a));
}
static __device__ __forceinline__ void ldsm4t(uint32_t* r, uint32_t a) {
    asm volatile("ldmatrix.sync.aligned.m8n8.x4.trans.shared.b16 {%0,%1,%2,%3}, [%4];"
                 : "=r"(r[0]), "=r"(r[1]), "=r"(r[2]), "=r"(r[3]) : "r"(a));
}
static __device__ __forceinline__ void mma16816(float* d, const uint32_t* a, const uint32_t* b) {
    asm volatile("mma.sync.aligned.m16n8k16.row.col.f32.f16.f16.f32 "
                 "{%0,%1,%2,%3}, {%4,%5,%6,%7}, {%8,%9}, {%0,%1,%2,%3};"
                 : "+f"(d[0]), "+f"(d[1]), "+f"(d[2]), "+f"(d[3])
                 : "r"(a[0]), "r"(a[1]), "r"(a[2]), "r"(a[3]), "r"(b[0]), "r"(b[1]));
}
static __device__ __forceinline__ uint32_t packh2(half a, half b) {
    half2 h = __halves2half2(a, b);
    return *reinterpret_cast<uint32_t*>(&h);
}

// stage one precomputed tile (Xh, Xl images + x2 row) into an smem buffer
static __device__ __forceinline__ void stage_tile(int tile, uint32_t sb,
                                                  uint32_t xhoff, int x2slot, int t) {
    const char* srcH = gXh + (size_t)tile * 16384;
    const char* srcL = gXl + (size_t)tile * 16384;
    #pragma unroll
    for (int k = 0; k < 4; k++) {
        int c = t + k * THREADS;          // 16B chunk id, 0..1023
        cp_async16(sb + xhoff + c * 16,         srcH + c * 16);
        cp_async16(sb + xhoff + 16384 + c * 16, srcL + c * 16);
    }
    if (t < 32) cp_async16(sb + OFF_X2 + x2slot * 512 + t * 16,
                           (const char*)(gx2 + (size_t)tile * 128) + t * 16);
    cp_commit();
}

// software grid barrier (all CTAs co-resident; grid sized by occupancy)
static __device__ __forceinline__ void gridbar(int nblk) {
    __syncthreads();
    if (threadIdx.x == 0) {
        unsigned gen = g_bar_gen;
        __threadfence();
        if (atomicAdd(&g_bar_cnt, 1u) == (unsigned)nblk - 1u) {
            g_bar_cnt = 0;
            __threadfence();
            g_bar_gen = gen + 1u;
        } else {
            while (g_bar_gen == gen) { __nanosleep(64); }
        }
    }
    __syncthreads();
}

// ---------------- one-shot precompute: fp32 -> swizzled fp16 hi/lo + norms ----
__global__ void __launch_bounds__(THREADS)
fcm_pre(const float* __restrict__ data, int N, int ntiles)
{
    const int t = threadIdx.x;
    for (int tile = blockIdx.x; tile < ntiles; tile += gridDim.x) {
        char* dstH = gXh + (size_t)tile * 16384;
        char* dstL = gXl + (size_t)tile * 16384;
        #pragma unroll
        for (int it = 0; it < 4; it++) {
            int i = t + it * THREADS;      // 0..1023
            int r = i >> 3, c = i & 7;     // row, 8-float chunk
            int grow = tile * 128 + r;
            float4 v0 = make_float4(0.f, 0.f, 0.f, 0.f), v1 = v0;
            if (grow < N) {
                const float4* p = reinterpret_cast<const float4*>(data + (size_t)grow * 64 + c * 8);
                v0 = p[0]; v1 = p[1];
            }
            float f[8] = {v0.x, v0.y, v0.z, v0.w, v1.x, v1.y, v1.z, v1.w};
            uint32_t hp[4], lp[4];
            #pragma unroll
            for (int k = 0; k < 4; k++) {
                half h0 = __float2half_rn(f[2*k]),   h1 = __float2half_rn(f[2*k+1]);
                half l0 = __float2half_rn(f[2*k]   - __half2float(h0));
                half l1 = __float2half_rn(f[2*k+1] - __half2float(h1));
                hp[k] = packh2(h0, h1);
                lp[k] = packh2(l0, l1);
            }
            uint32_t off = swz(r, c * 8);
            *reinterpret_cast<uint4*>(dstH + off) = make_uint4(hp[0], hp[1], hp[2], hp[3]);
            *reinterpret_cast<uint4*>(dstL + off) = make_uint4(lp[0], lp[1], lp[2], lp[3]);
            float sq = 0.f;
            #pragma unroll
            for (int k = 0; k < 8; k++) sq += f[k] * f[k];
            sq += __shfl_xor_sync(0xFFFFFFFFu, sq, 1);
            sq += __shfl_xor_sync(0xFFFFFFFFu, sq, 2);
            sq += __shfl_xor_sync(0xFFFFFFFFu, sq, 4);
            if (c == 0) gx2[(size_t)tile * 128 + r] = sq;
        }
    }
}

// ---------------- persistent fused kernel: all 26 iterations ----------------
__global__ void __launch_bounds__(THREADS, 2)
fcm_persist(const float* __restrict__ u0, int N, float* __restrict__ out)
{
    extern __shared__ char smem[];
    const uint32_t sb = smem_u32(smem);
    float* x2s = (float*)(smem + OFF_X2);
    float* c2s = (float*)(smem + OFF_C2);

    const int t = threadIdx.x;
    const int w = t >> 5, lane = t & 31;
    const int quad = lane >> 2, qid = lane & 3;
    const int seg = lane >> 3, q = lane & 7;
    const int bucket = blockIdx.x & (NBUCKET - 1);
    const int nblk = gridDim.x;
    const int ntiles = (N + 127) >> 7;
    const int jm = (w & 3) * 16;        // GEMM2 m-tile (j rows)
    const int nb = (w >> 2) * 4;        // GEMM2 n-tile base (d/8)

    if (blockIdx.x == 0 && t == 0) g_done = 0;

    for (int iter = 0; iter <= 25; iter++) {
        const int mode = (iter > 0);

        float G[4][4];
        #pragma unroll
        for (int a = 0; a < 4; a++)
            #pragma unroll
            for (int b = 0; b < 4; b++) G[a][b] = 0.f;
        float DEN[4] = {0.f, 0.f, 0.f, 0.f};

        // prologue: stage first tile into buf0
        if (blockIdx.x < ntiles) stage_tile(blockIdx.x, sb, OFF_XH0, 0, t);

        int buf = 0;
        for (int tile = blockIdx.x; tile < ntiles; tile += nblk) {
            cp_wait0();
            __syncthreads();   // buf's X tiles visible; previous GEMM2 reads done

            const uint32_t xhoff = buf ? OFF_XH1 : OFF_XH0;
            const uint32_t xloff = xhoff + 16384;

            // prefetch next tile into the other buffer (overlaps everything below)
            int ntile = tile + nblk;
            if (ntile < ntiles) stage_tile(ntile, sb, buf ? OFF_XH0 : OFF_XH1, buf ^ 1, t);

            // ---- memberships ----
            float S[8][4];
            const int r1l = 16 * w + quad;
            const int grow1 = tile * 128 + r1l;
            const int grow2 = grow1 + 8;

            if (mode) {
                #pragma unroll
                for (int tn = 0; tn < 8; tn++)
                    #pragma unroll
                    for (int b = 0; b < 4; b++) S[tn][b] = 0.f;
                // GEMM1 single chain: S = Xh.Ch^T  (warp w: rows 16w..16w+15)
                #pragma unroll
                for (int kk = 0; kk < 4; kk++) {
                    uint32_t ah[4];
                    ldsm4(ah, sb + xhoff + swz(16 * w + (seg & 1) * 8 + q,
                                               kk * 16 + (seg >> 1) * 8));
                    #pragma unroll
                    for (int tnp = 0; tnp < 4; tnp++) {
                        uint32_t bb[4];
                        ldsm4(bb, sb + OFF_CH + swz(16 * tnp + ((lane >> 4) << 3) + q,
                                                    kk * 16 + ((lane >> 3) & 1) * 8));
                        mma16816(S[2 * tnp],     ah, bb);
                        mma16816(S[2 * tnp + 1], ah, bb + 2);
                    }
                }
                float xx1 = x2s[buf * 128 + r1l], xx2 = x2s[buf * 128 + r1l + 8];
                #pragma unroll
                for (int tn = 0; tn < 8; tn++) {
                    int j = 8 * tn + qid * 2;
                    float ca = c2s[j], cb = c2s[j + 1];
                    S[tn][0] = frcp(fmaxf(xx1 + ca - 2.f * S[tn][0], 0.f));
                    S[tn][1] = frcp(fmaxf(xx1 + cb - 2.f * S[tn][1], 0.f));
                    S[tn][2] = frcp(fmaxf(xx2 + ca - 2.f * S[tn][2], 0.f));
                    S[tn][3] = frcp(fmaxf(xx2 + cb - 2.f * S[tn][3], 0.f));
                }
            } else {
                #pragma unroll
                for (int tn = 0; tn < 8; tn++) {
                    int j = 8 * tn + qid * 2;
                    float2 p1 = make_float2(0.f, 0.f), p2 = p1;
                    if (grow1 < N) p1 = *reinterpret_cast<const float2*>(u0 + (size_t)grow1 * 64 + j);
                    if (grow2 < N) p2 = *reinterpret_cast<const float2*>(u0 + (size_t)grow2 * 64 + j);
                    S[tn][0] = p1.x; S[tn][1] = p1.y; S[tn][2] = p2.x; S[tn][3] = p2.y;
                }
            }

            float s1 = 0.f, s2 = 0.f;
            #pragma unroll
            for (int tn = 0; tn < 8; tn++) { s1 += S[tn][0] + S[tn][1]; s2 += S[tn][2] + S[tn][3]; }
            s1 += __shfl_xor_sync(0xFFFFFFFFu, s1, 1);
            s1 += __shfl_xor_sync(0xFFFFFFFFu, s1, 2);
            s2 += __shfl_xor_sync(0xFFFFFFFFu, s2, 1);
            s2 += __shfl_xor_sync(0xFFFFFFFFu, s2, 2);
            float i1 = (grow1 < N) ? frcp(s1) : 0.f;
            float i2 = (grow2 < N) ? frcp(s2) : 0.f;

            #pragma unroll
            for (int tn = 0; tn < 8; tn++) {
                int j = 8 * tn + qid * 2;
                float ua0 = S[tn][0] * i1; ua0 *= ua0;
                float ua1 = S[tn][1] * i1; ua1 *= ua1;
                float ub0 = S[tn][2] * i2; ub0 *= ub0;
                float ub1 = S[tn][3] * i2; ub1 *= ub1;
                half ha0 = __float2half_rn(ua0), ha1 = __float2half_rn(ua1);
                half hb0 = __float2half_rn(ub0), hb1 = __float2half_rn(ub1);
                half la0 = __float2half_rn(ua0 - __half2float(ha0));
                half la1 = __float2half_rn(ua1 - __half2float(ha1));
                half lb0 = __float2half_rn(ub0 - __half2float(hb0));
                half lb1 = __float2half_rn(ub1 - __half2float(hb1));
                uint32_t o1 = swz(r1l, j), o2 = swz(r1l + 8, j);
                *(uint32_t*)(smem + OFF_UH + o1) = packh2(ha0, ha1);
                *(uint32_t*)(smem + OFF_UL + o1) = packh2(la0, la1);
                *(uint32_t*)(smem + OFF_UH + o2) = packh2(hb0, hb1);
                *(uint32_t*)(smem + OFF_UL + o2) = packh2(lb0, lb1);
            }
            __syncthreads();   // U visible

            // ---- GEMM2: G += U^T X (3 chains); den += Uh^T ones ----
            {
                const uint32_t ones[2] = {0x3C003C00u, 0x3C003C00u};
                #pragma unroll
                for (int rr = 0; rr < 8; rr++) {
                    int ur = rr * 16 + (seg >> 1) * 8 + q;
                    int uc = jm + (seg & 1) * 8;
                    uint32_t uoff = sb + swz(ur, uc);
                    uint32_t auh[4], aul[4];
                    ldsm4t(auh, uoff + OFF_UH);
                    ldsm4t(aul, uoff + OFF_UL);
                    #pragma unroll
                    for (int tnp = 0; tnp < 2; tnp++) {
                        int d0 = 8 * (nb + 2 * tnp);
                        uint32_t xoff = swz(rr * 16 + ((lane >> 3) & 1) * 8 + q,
                                            d0 + (lane >> 4) * 8);
                        uint32_t bxh[4], bxl[4];
                        ldsm4t(bxh, sb + xhoff + xoff);
                        ldsm4t(bxl, sb + xloff + xoff);
                        mma16816(G[2 * tnp],     auh, bxh);
                        mma16816(G[2 * tnp],     auh, bxl);
                        mma16816(G[2 * tnp],     aul, bxh);
                        mma16816(G[2 * tnp + 1], auh, bxh + 2);
                        mma16816(G[2 * tnp + 1], auh, bxl + 2);
                        mma16816(G[2 * tnp + 1], aul, bxh + 2);
                    }
                    if (w < 4) mma16816(DEN, auh, ones);
                }
            }
            buf ^= 1;
        }

        // ---- flush block partials (bucketed atomics) ----
        {
            int j1 = jm + quad;
            #pragma unroll
            for (int tn = 0; tn < 4; tn++) {
                int d = 8 * (nb + tn) + qid * 2;
                atomicAdd(&g_part[bucket][j1 * 64 + d],           G[tn][0]);
                atomicAdd(&g_part[bucket][j1 * 64 + d + 1],       G[tn][1]);
                atomicAdd(&g_part[bucket][(j1 + 8) * 64 + d],     G[tn][2]);
                atomicAdd(&g_part[bucket][(j1 + 8) * 64 + d + 1], G[tn][3]);
            }
            if (w < 4 && qid == 0) {
                atomicAdd(&g_denp[bucket][j1],     DEN[0]);
                atomicAdd(&g_denp[bucket][j1 + 8], DEN[2]);
            }
        }

        gridbar(nblk);

        // ---- distributed center: block j computes cluster row j ----
        const int pnew = iter & 1, pold = pnew ^ 1;
        if (blockIdx.x < 64 && t < 64) {
            const int j = blockIdx.x, d = t;
            float num = 0.f, den = 0.f;
            #pragma unroll
            for (int b = 0; b < NBUCKET; b++) {
                num += g_part[b][j * 64 + d];
                g_part[b][j * 64 + d] = 0.f;
                den += g_denp[b][j];
            }
            if (t < NBUCKET) g_denp[t][j] = 0.f;
            float c = num / den;
            g_C[pnew][j * 64 + d] = c;
            if (iter > 0) {
                float dd = c - g_C[pold][j * 64 + d];
                float s = dd * dd;
                #pragma unroll
                for (int m = 16; m > 0; m >>= 1) s += __shfl_xor_sync(0xFFFFFFFFu, s, m);
                if ((t & 31) == 0) atomicAdd(&g_diff, s);
            }
        }

        gridbar(nblk);

        // ---- convergence latch (block 0; out tracks C_{k-1}, frozen once done) ----
        if (blockIdx.x == 0 && iter > 0) {
            int done = g_done;
            __syncthreads();
            if (!done)
                for (int i = t; i < 4096; i += THREADS) out[i] = g_C[pold][i];
            __syncthreads();
            if (t == 0) {
                float df = g_diff;
                if (!done && sqrtf(df) < 1e-8f) g_done = 1;
                g_diff = 0.f;
            }
        }

        // ---- build C tile for next pass ----
        if (iter < 25) {
            const float* C = g_C[pnew];
            for (int i = t; i < 4096; i += THREADS) {
                int j = i >> 6, d = i & 63;
                *(half*)(smem + OFF_CH + swz(j, d)) = __float2half_rn(C[i]);
            }
            if (t < 64) {
                const float* Cr = C + t * 64;
                float s = 0.f;
                #pragma unroll 8
                for (int d = 0; d < 64; d++) s += Cr[d] * Cr[d];
                c2s[t] = s;
            }
            __syncthreads();
        }
    }

    // ---- final: if never converged, answer is C_25 ----
    if (blockIdx.x == 0) {
        __syncthreads();
        if (!g_done)
            for (int i = t; i < 4096; i += THREADS) out[i] = g_C[1][i];
    }
}

// ---------------- host launch ----------------
extern "C" void kernel_launch(void* const* d_in, const int* in_sizes, int n_in,
                              void* d_out, int out_size) {
    const float* data = (const float*)d_in[0];
    const float* u0   = (const float*)d_in[1];
    const int N = in_sizes[0] / 64;     // 300000
    float* out = (float*)d_out;
    const int ntiles = (N + 127) >> 7;

    cudaFuncSetAttribute(fcm_persist, cudaFuncAttributeMaxDynamicSharedMemorySize, SMEM_BYTES);

    int nbsm = 0;
    cudaOccupancyMaxActiveBlocksPerMultiprocessor(&nbsm, fcm_persist, THREADS, SMEM_BYTES);
    if (nbsm < 1) nbsm = 1;
    if (nbsm > 2) nbsm = 2;
    int dev = 0, nsm = 148;
    cudaGetDevice(&dev);
    cudaDeviceGetAttribute(&nsm, cudaDevAttrMultiProcessorCount, dev);
    int grid = nbsm * nsm;   // all CTAs co-resident -> software grid barrier is safe

    fcm_pre<<<grid, THREADS>>>(data, N, ntiles);
    fcm_persist<<<grid, THREADS, SMEM_BYTES>>>(u0, N, out);
}

// round 8
// speedup vs baseline: 5.2814x; 1.2563x over previous
#include <cuda_runtime.h>
#include <cuda_fp16.h>
#include <cstdint>

#define THREADS 256
#define NBUCKET 16
#define MAXTILES 2350   // >= ceil(300000/128)

// ---------------- device-global state (no allocations allowed) ----------------
__device__ float g_C[2][64 * 64];
__device__ float g_part[NBUCKET][64 * 64];
__device__ float g_denp[NBUCKET][64];
__device__ float g_diff;
__device__ int   g_done;
__device__ unsigned g_bar_cnt;
__device__ volatile unsigned g_bar_gen;

// precomputed fp16 X (hi part), per-tile swizzled smem images (16 KB each) + exact norms
__device__ char  gXh[(size_t)MAXTILES * 16384];
__device__ float gx2[(size_t)MAXTILES * 128];

// ---------------- smem layout (bytes) ----------------
#define OFF_XH0   0        // X hi buf0 [128][64] half swizzled, 16 KB
#define OFF_XH1   16384
#define OFF_UH    32768    // U^2 hi [128 r][64 j] half swizzled, 16 KB
#define OFF_CH    49152    // C hi [64][64] half swizzled, 8 KB
#define OFF_X2    57344    // float[2][128]
#define OFF_C2    58368    // float[64]
#define SMEM_BYTES 58624

// XOR swizzle: 16B-chunk permutation within a 128B row (conflict-free ldmatrix)
static __device__ __forceinline__ uint32_t swz(int r, int colhalf) {
    return (uint32_t)(r * 128 + ((colhalf * 2) ^ ((r & 7) << 4)));
}
static __device__ __forceinline__ uint32_t smem_u32(const void* p) {
    uint32_t a;
    asm("{ .reg .u64 t; cvta.to.shared.u64 t, %1; cvt.u32.u64 %0, t; }" : "=r"(a) : "l"(p));
    return a;
}
static __device__ __forceinline__ float frcp(float x) {
    float y;
    asm("rcp.approx.f32 %0, %1;" : "=f"(y) : "f"(x));
    return y;
}

// ---------------- cp.async ----------------
static __device__ __forceinline__ void cp_async16(uint32_t dst, const void* src) {
    asm volatile("cp.async.cg.shared.global [%0], [%1], 16;"
                 :: "r"(dst), "l"(src) : "memory");
}
static __device__ __forceinline__ void cp_commit() {
    asm volatile("cp.async.commit_group;" ::: "memory");
}
static __device__ __forceinline__ void cp_wait0() {
    asm volatile("cp.async.wait_group 0;" ::: "memory");
}

// ---------------- mma / ldmatrix wrappers ----------------
static __device__ __forceinline__ void ldsm4(uint32_t* r, uint32_t a) {
    asm volatile("ldmatrix.sync.aligned.m8n8.x4.shared.b16 {%0,%1,%2,%3}, [%4];"
                 : "=r"(r[0]), "=r"(r[1]), "=r"(r[2]), "=r"(r[3]) : "r"(a));
}
static __device__ __forceinline__ void ldsm4t(uint32_t* r, uint32_t a) {
    asm volatile("ldmatrix.sync.aligned.m8n8.x4.trans.shared.b16 {%0,%1,%2,%3}, [%4];"
                 : "=r"(r[0]), "=r"(r[1]), "=r"(r[2]), "=r"(r[3]) : "r"(a));
}
static __device__ __forceinline__ void mma16816(float* d, const uint32_t* a, const uint32_t* b) {
    asm volatile("mma.sync.aligned.m16n8k16.row.col.f32.f16.f16.f32 "
                 "{%0,%1,%2,%3}, {%4,%5,%6,%7}, {%8,%9}, {%0,%1,%2,%3};"
                 : "+f"(d[0]), "+f"(d[1]), "+f"(d[2]), "+f"(d[3])
                 : "r"(a[0]), "r"(a[1]), "r"(a[2]), "r"(a[3]), "r"(b[0]), "r"(b[1]));
}
static __device__ __forceinline__ uint32_t packh2(half a, half b) {
    half2 h = __halves2half2(a, b);
    return *reinterpret_cast<uint32_t*>(&h);
}

// stage one precomputed tile (Xh image + x2 row) into an smem buffer
static __device__ __forceinline__ void stage_tile(int tile, uint32_t sb,
                                                  uint32_t xhoff, int x2slot, int t) {
    const char* srcH = gXh + (size_t)tile * 16384;
    #pragma unroll
    for (int k = 0; k < 4; k++) {
        int c = t + k * THREADS;          // 16B chunk id, 0..1023
        cp_async16(sb + xhoff + c * 16, srcH + c * 16);
    }
    if (t < 32) cp_async16(sb + OFF_X2 + x2slot * 512 + t * 16,
                           (const char*)(gx2 + (size_t)tile * 128) + t * 16);
    cp_commit();
}

// software grid barrier (all CTAs co-resident; grid sized by occupancy)
static __device__ __forceinline__ void gridbar(int nblk) {
    __syncthreads();
    if (threadIdx.x == 0) {
        unsigned gen = g_bar_gen;
        __threadfence();
        if (atomicAdd(&g_bar_cnt, 1u) == (unsigned)nblk - 1u) {
            g_bar_cnt = 0;
            __threadfence();
            g_bar_gen = gen + 1u;
        } else {
            while (g_bar_gen == gen) { __nanosleep(64); }
        }
    }
    __syncthreads();
}

// ---------------- one-shot precompute: fp32 -> swizzled fp16 hi + exact norms ----
__global__ void __launch_bounds__(THREADS)
fcm_pre(const float* __restrict__ data, int N, int ntiles)
{
    const int t = threadIdx.x;
    for (int tile = blockIdx.x; tile < ntiles; tile += gridDim.x) {
        char* dstH = gXh + (size_t)tile * 16384;
        #pragma unroll
        for (int it = 0; it < 4; it++) {
            int i = t + it * THREADS;      // 0..1023
            int r = i >> 3, c = i & 7;     // row, 8-float chunk
            int grow = tile * 128 + r;
            float4 v0 = make_float4(0.f, 0.f, 0.f, 0.f), v1 = v0;
            if (grow < N) {
                const float4* p = reinterpret_cast<const float4*>(data + (size_t)grow * 64 + c * 8);
                v0 = p[0]; v1 = p[1];
            }
            float f[8] = {v0.x, v0.y, v0.z, v0.w, v1.x, v1.y, v1.z, v1.w};
            uint32_t hp[4];
            #pragma unroll
            for (int k = 0; k < 4; k++)
                hp[k] = packh2(__float2half_rn(f[2*k]), __float2half_rn(f[2*k+1]));
            *reinterpret_cast<uint4*>(dstH + swz(r, c * 8)) = make_uint4(hp[0], hp[1], hp[2], hp[3]);
            float sq = 0.f;
            #pragma unroll
            for (int k = 0; k < 8; k++) sq += f[k] * f[k];
            sq += __shfl_xor_sync(0xFFFFFFFFu, sq, 1);
            sq += __shfl_xor_sync(0xFFFFFFFFu, sq, 2);
            sq += __shfl_xor_sync(0xFFFFFFFFu, sq, 4);
            if (c == 0) gx2[(size_t)tile * 128 + r] = sq;
        }
    }
}

// ---------------- persistent fused kernel: all 26 iterations ----------------
__global__ void __launch_bounds__(THREADS, 3)
fcm_persist(const float* __restrict__ u0, int N, float* __restrict__ out)
{
    extern __shared__ char smem[];
    const uint32_t sb = smem_u32(smem);
    float* x2s = (float*)(smem + OFF_X2);
    float* c2s = (float*)(smem + OFF_C2);

    const int t = threadIdx.x;
    const int w = t >> 5, lane = t & 31;
    const int quad = lane >> 2, qid = lane & 3;
    const int seg = lane >> 3, q = lane & 7;
    const int bucket = blockIdx.x & (NBUCKET - 1);
    const int nblk = gridDim.x;
    const int ntiles = (N + 127) >> 7;
    const int jm = (w & 3) * 16;        // GEMM2 m-tile (j rows)
    const int nb = (w >> 2) * 4;        // GEMM2 n-tile base (d/8)

    if (blockIdx.x == 0 && t == 0) g_done = 0;

    for (int iter = 0; iter <= 25; iter++) {
        const int mode = (iter > 0);

        float G[4][4];
        #pragma unroll
        for (int a = 0; a < 4; a++)
            #pragma unroll
            for (int b = 0; b < 4; b++) G[a][b] = 0.f;
        float DEN[4] = {0.f, 0.f, 0.f, 0.f};

        // prologue: stage first tile into buf0
        if (blockIdx.x < ntiles) stage_tile(blockIdx.x, sb, OFF_XH0, 0, t);

        int buf = 0;
        for (int tile = blockIdx.x; tile < ntiles; tile += nblk) {
            cp_wait0();
            __syncthreads();   // buf's X tile visible; previous GEMM2 reads done

            const uint32_t xhoff = buf ? OFF_XH1 : OFF_XH0;

            // prefetch next tile into the other buffer (overlaps everything below)
            int ntile = tile + nblk;
            if (ntile < ntiles) stage_tile(ntile, sb, buf ? OFF_XH0 : OFF_XH1, buf ^ 1, t);

            // ---- memberships ----
            float S[8][4];
            const int r1l = 16 * w + quad;
            const int grow1 = tile * 128 + r1l;
            const int grow2 = grow1 + 8;

            if (mode) {
                #pragma unroll
                for (int tn = 0; tn < 8; tn++)
                    #pragma unroll
                    for (int b = 0; b < 4; b++) S[tn][b] = 0.f;
                // GEMM1 single chain: S = Xh.Ch^T  (warp w: rows 16w..16w+15)
                #pragma unroll
                for (int kk = 0; kk < 4; kk++) {
                    uint32_t ah[4];
                    ldsm4(ah, sb + xhoff + swz(16 * w + (seg & 1) * 8 + q,
                                               kk * 16 + (seg >> 1) * 8));
                    #pragma unroll
                    for (int tnp = 0; tnp < 4; tnp++) {
                        uint32_t bb[4];
                        ldsm4(bb, sb + OFF_CH + swz(16 * tnp + ((lane >> 4) << 3) + q,
                                                    kk * 16 + ((lane >> 3) & 1) * 8));
                        mma16816(S[2 * tnp],     ah, bb);
                        mma16816(S[2 * tnp + 1], ah, bb + 2);
                    }
                }
                float xx1 = x2s[buf * 128 + r1l], xx2 = x2s[buf * 128 + r1l + 8];
                #pragma unroll
                for (int tn = 0; tn < 8; tn++) {
                    int j = 8 * tn + qid * 2;
                    float ca = c2s[j], cb = c2s[j + 1];
                    S[tn][0] = frcp(fmaxf(xx1 + ca - 2.f * S[tn][0], 0.f));
                    S[tn][1] = frcp(fmaxf(xx1 + cb - 2.f * S[tn][1], 0.f));
                    S[tn][2] = frcp(fmaxf(xx2 + ca - 2.f * S[tn][2], 0.f));
                    S[tn][3] = frcp(fmaxf(xx2 + cb - 2.f * S[tn][3], 0.f));
                }
            } else {
                #pragma unroll
                for (int tn = 0; tn < 8; tn++) {
                    int j = 8 * tn + qid * 2;
                    float2 p1 = make_float2(0.f, 0.f), p2 = p1;
                    if (grow1 < N) p1 = *reinterpret_cast<const float2*>(u0 + (size_t)grow1 * 64 + j);
                    if (grow2 < N) p2 = *reinterpret_cast<const float2*>(u0 + (size_t)grow2 * 64 + j);
                    S[tn][0] = p1.x; S[tn][1] = p1.y; S[tn][2] = p2.x; S[tn][3] = p2.y;
                }
            }

            float s1 = 0.f, s2 = 0.f;
            #pragma unroll
            for (int tn = 0; tn < 8; tn++) { s1 += S[tn][0] + S[tn][1]; s2 += S[tn][2] + S[tn][3]; }
            s1 += __shfl_xor_sync(0xFFFFFFFFu, s1, 1);
            s1 += __shfl_xor_sync(0xFFFFFFFFu, s1, 2);
            s2 += __shfl_xor_sync(0xFFFFFFFFu, s2, 1);
            s2 += __shfl_xor_sync(0xFFFFFFFFu, s2, 2);
            float i1 = (grow1 < N) ? frcp(s1) : 0.f;
            float i2 = (grow2 < N) ? frcp(s2) : 0.f;

            // u^2 -> fp16 (hi only) -> smem U tile
            #pragma unroll
            for (int tn = 0; tn < 8; tn++) {
                int j = 8 * tn + qid * 2;
                float ua0 = S[tn][0] * i1; ua0 *= ua0;
                float ua1 = S[tn][1] * i1; ua1 *= ua1;
                float ub0 = S[tn][2] * i2; ub0 *= ub0;
                float ub1 = S[tn][3] * i2; ub1 *= ub1;
                *(uint32_t*)(smem + OFF_UH + swz(r1l, j)) =
                    packh2(__float2half_rn(ua0), __float2half_rn(ua1));
                *(uint32_t*)(smem + OFF_UH + swz(r1l + 8, j)) =
                    packh2(__float2half_rn(ub0), __float2half_rn(ub1));
            }
            __syncthreads();   // U visible

            // ---- GEMM2 single chain: G += Uh^T Xh ; den += Uh^T ones ----
            {
                const uint32_t ones[2] = {0x3C003C00u, 0x3C003C00u};
                #pragma unroll
                for (int rr = 0; rr < 8; rr++) {
                    int ur = rr * 16 + (seg >> 1) * 8 + q;
                    int uc = jm + (seg & 1) * 8;
                    uint32_t auh[4];
                    ldsm4t(auh, sb + OFF_UH + swz(ur, uc));
                    #pragma unroll
                    for (int tnp = 0; tnp < 2; tnp++) {
                        int d0 = 8 * (nb + 2 * tnp);
                        uint32_t bxh[4];
                        ldsm4t(bxh, sb + xhoff + swz(rr * 16 + ((lane >> 3) & 1) * 8 + q,
                                                     d0 + (lane >> 4) * 8));
                        mma16816(G[2 * tnp],     auh, bxh);
                        mma16816(G[2 * tnp + 1], auh, bxh + 2);
                    }
                    if (w < 4) mma16816(DEN, auh, ones);
                }
            }
            buf ^= 1;
        }

        // ---- flush block partials (bucketed atomics) ----
        {
            int j1 = jm + quad;
            #pragma unroll
            for (int tn = 0; tn < 4; tn++) {
                int d = 8 * (nb + tn) + qid * 2;
                atomicAdd(&g_part[bucket][j1 * 64 + d],           G[tn][0]);
                atomicAdd(&g_part[bucket][j1 * 64 + d + 1],       G[tn][1]);
                atomicAdd(&g_part[bucket][(j1 + 8) * 64 + d],     G[tn][2]);
                atomicAdd(&g_part[bucket][(j1 + 8) * 64 + d + 1], G[tn][3]);
            }
            if (w < 4 && qid == 0) {
                atomicAdd(&g_denp[bucket][j1],     DEN[0]);
                atomicAdd(&g_denp[bucket][j1 + 8], DEN[2]);
            }
        }

        gridbar(nblk);

        // ---- distributed center: block j computes cluster row j ----
        const int pnew = iter & 1, pold = pnew ^ 1;
        if (blockIdx.x < 64 && t < 64) {
            const int j = blockIdx.x, d = t;
            float num = 0.f, den = 0.f;
            #pragma unroll
            for (int b = 0; b < NBUCKET; b++) {
                num += g_part[b][j * 64 + d];
                g_part[b][j * 64 + d] = 0.f;
                den += g_denp[b][j];
            }
            if (t < NBUCKET) g_denp[t][j] = 0.f;
            float c = num / den;
            g_C[pnew][j * 64 + d] = c;
            if (iter > 0) {
                float dd = c - g_C[pold][j * 64 + d];
                float s = dd * dd;
                #pragma unroll
                for (int m = 16; m > 0; m >>= 1) s += __shfl_xor_sync(0xFFFFFFFFu, s, m);
                if ((t & 31) == 0) atomicAdd(&g_diff, s);
            }
        }

        gridbar(nblk);

        // ---- convergence latch (block 0; out tracks C_{k-1}, frozen once done) ----
        if (blockIdx.x == 0 && iter > 0) {
            int done = g_done;
            __syncthreads();
            if (!done)
                for (int i = t; i < 4096; i += THREADS) out[i] = g_C[pold][i];
            __syncthreads();
            if (t == 0) {
                float df = g_diff;
                if (!done && sqrtf(df) < 1e-8f) g_done = 1;
                g_diff = 0.f;
            }
        }

        // ---- build C tile for next pass ----
        if (iter < 25) {
            const float* C = g_C[pnew];
            for (int i = t; i < 4096; i += THREADS) {
                int j = i >> 6, d = i & 63;
                *(half*)(smem + OFF_CH + swz(j, d)) = __float2half_rn(C[i]);
            }
            if (t < 64) {
                const float* Cr = C + t * 64;
                float s = 0.f;
                #pragma unroll 8
                for (int d = 0; d < 64; d++) s += Cr[d] * Cr[d];
                c2s[t] = s;
            }
            __syncthreads();
        }
    }

    // ---- final: if never converged, answer is C_25 ----
    if (blockIdx.x == 0) {
        __syncthreads();
        if (!g_done)
            for (int i = t; i < 4096; i += THREADS) out[i] = g_C[1][i];
    }
}

// ---------------- host launch ----------------
extern "C" void kernel_launch(void* const* d_in, const int* in_sizes, int n_in,
                              void* d_out, int out_size) {
    const float* data = (const float*)d_in[0];
    const float* u0   = (const float*)d_in[1];
    const int N = in_sizes[0] / 64;     // 300000
    float* out = (float*)d_out;
    const int ntiles = (N + 127) >> 7;

    cudaFuncSetAttribute(fcm_persist, cudaFuncAttributeMaxDynamicSharedMemorySize, SMEM_BYTES);

    int nbsm = 0;
    cudaOccupancyMaxActiveBlocksPerMultiprocessor(&nbsm, fcm_persist, THREADS, SMEM_BYTES);
    if (nbsm < 1) nbsm = 1;
    if (nbsm > 3) nbsm = 3;
    int dev = 0, nsm = 148;
    cudaGetDevice(&dev);
    cudaDeviceGetAttribute(&nsm, cudaDevAttrMultiProcessorCount, dev);
    int grid = nbsm * nsm;   // all CTAs co-resident -> software grid barrier is safe

    fcm_pre<<<grid, THREADS>>>(data, N, ntiles);
    fcm_persist<<<grid, THREADS, SMEM_BYTES>>>(u0, N, out);
}

// round 9
// speedup vs baseline: 5.8631x; 1.1101x over previous
#include <cuda_runtime.h>
#include <cuda_fp16.h>
#include <cstdint>

#define THREADS 256
#define MAXTILES 2350   // >= ceil(300000/128)
#define MAXBLK   512

// ---------------- device-global state (no allocations allowed) ----------------
__device__ float g_C[2][64 * 64];
__device__ float g_slab[MAXBLK][64 * 64];   // per-block GEMM2 partials (plain STG)
__device__ float g_dslab[MAXBLK][64];       // per-block den partials
__device__ float g_diff;
__device__ int   g_done;
__device__ unsigned g_bar_cnt;
__device__ volatile unsigned g_bar_gen;

// precomputed fp16 X (hi part), per-tile swizzled smem images (16 KB each) + exact norms
__device__ char  gXh[(size_t)MAXTILES * 16384];
__device__ float gx2[(size_t)MAXTILES * 128];

// ---------------- smem layout (bytes) ----------------
#define OFF_XH0   0        // X hi buf0 [128][64] half swizzled, 16 KB
#define OFF_XH1   16384
#define OFF_UH    32768    // U^2 hi [128 r][64 j] half swizzled, 16 KB (reused as sred in center)
#define OFF_CH    49152    // C hi [64][64] half swizzled, 8 KB
#define OFF_X2    57344    // float[2][128]
#define OFF_C2    58368    // float[64]
#define SMEM_BYTES 58624

// XOR swizzle: 16B-chunk permutation within a 128B row (conflict-free ldmatrix)
static __device__ __forceinline__ uint32_t swz(int r, int colhalf) {
    return (uint32_t)(r * 128 + ((colhalf * 2) ^ ((r & 7) << 4)));
}
static __device__ __forceinline__ uint32_t smem_u32(const void* p) {
    uint32_t a;
    asm("{ .reg .u64 t; cvta.to.shared.u64 t, %1; cvt.u32.u64 %0, t; }" : "=r"(a) : "l"(p));
    return a;
}
static __device__ __forceinline__ float frcp(float x) {
    float y;
    asm("rcp.approx.f32 %0, %1;" : "=f"(y) : "f"(x));
    return y;
}

// ---------------- cp.async ----------------
static __device__ __forceinline__ void cp_async16(uint32_t dst, const void* src) {
    asm volatile("cp.async.cg.shared.global [%0], [%1], 16;"
                 :: "r"(dst), "l"(src) : "memory");
}
static __device__ __forceinline__ void cp_commit() {
    asm volatile("cp.async.commit_group;" ::: "memory");
}
static __device__ __forceinline__ void cp_wait0() {
    asm volatile("cp.async.wait_group 0;" ::: "memory");
}

// ---------------- mma / ldmatrix wrappers ----------------
static __device__ __forceinline__ void ldsm4(uint32_t* r, uint32_t a) {
    asm volatile("ldmatrix.sync.aligned.m8n8.x4.shared.b16 {%0,%1,%2,%3}, [%4];"
                 : "=r"(r[0]), "=r"(r[1]), "=r"(r[2]), "=r"(r[3]) : "r"(a));
}
static __device__ __forceinline__ void ldsm4t(uint32_t* r, uint32_t a) {
    asm volatile("ldmatrix.sync.aligned.m8n8.x4.trans.shared.b16 {%0,%1,%2,%3}, [%4];"
                 : "=r"(r[0]), "=r"(r[1]), "=r"(r[2]), "=r"(r[3]) : "r"(a));
}
static __device__ __forceinline__ void mma16816(float* d, const uint32_t* a, const uint32_t* b) {
    asm volatile("mma.sync.aligned.m16n8k16.row.col.f32.f16.f16.f32 "
                 "{%0,%1,%2,%3}, {%4,%5,%6,%7}, {%8,%9}, {%0,%1,%2,%3};"
                 : "+f"(d[0]), "+f"(d[1]), "+f"(d[2]), "+f"(d[3])
                 : "r"(a[0]), "r"(a[1]), "r"(a[2]), "r"(a[3]), "r"(b[0]), "r"(b[1]));
}
static __device__ __forceinline__ uint32_t packh2(half a, half b) {
    half2 h = __halves2half2(a, b);
    return *reinterpret_cast<uint32_t*>(&h);
}

// stage one precomputed tile (Xh image + x2 row) into an smem buffer
static __device__ __forceinline__ void stage_tile(int tile, uint32_t sb,
                                                  uint32_t xhoff, int x2slot, int t) {
    const char* srcH = gXh + (size_t)tile * 16384;
    #pragma unroll
    for (int k = 0; k < 4; k++) {
        int c = t + k * THREADS;          // 16B chunk id, 0..1023
        cp_async16(sb + xhoff + c * 16, srcH + c * 16);
    }
    if (t < 32) cp_async16(sb + OFF_X2 + x2slot * 512 + t * 16,
                           (const char*)(gx2 + (size_t)tile * 128) + t * 16);
    cp_commit();
}

// software grid barrier (all CTAs co-resident; grid sized by occupancy)
static __device__ __forceinline__ void gridbar(int nblk) {
    __syncthreads();
    if (threadIdx.x == 0) {
        unsigned gen = g_bar_gen;
        __threadfence();
        if (atomicAdd(&g_bar_cnt, 1u) == (unsigned)nblk - 1u) {
            g_bar_cnt = 0;
            __threadfence();
            g_bar_gen = gen + 1u;
        } else {
            while (g_bar_gen == gen) { __nanosleep(64); }
        }
    }
    __syncthreads();
}

// ---------------- one-shot precompute: fp32 -> swizzled fp16 hi + exact norms ----
__global__ void __launch_bounds__(THREADS)
fcm_pre(const float* __restrict__ data, int N, int ntiles)
{
    const int t = threadIdx.x;
    for (int tile = blockIdx.x; tile < ntiles; tile += gridDim.x) {
        char* dstH = gXh + (size_t)tile * 16384;
        #pragma unroll
        for (int it = 0; it < 4; it++) {
            int i = t + it * THREADS;      // 0..1023
            int r = i >> 3, c = i & 7;     // row, 8-float chunk
            int grow = tile * 128 + r;
            float4 v0 = make_float4(0.f, 0.f, 0.f, 0.f), v1 = v0;
            if (grow < N) {
                const float4* p = reinterpret_cast<const float4*>(data + (size_t)grow * 64 + c * 8);
                v0 = p[0]; v1 = p[1];
            }
            float f[8] = {v0.x, v0.y, v0.z, v0.w, v1.x, v1.y, v1.z, v1.w};
            uint32_t hp[4];
            #pragma unroll
            for (int k = 0; k < 4; k++)
                hp[k] = packh2(__float2half_rn(f[2*k]), __float2half_rn(f[2*k+1]));
            *reinterpret_cast<uint4*>(dstH + swz(r, c * 8)) = make_uint4(hp[0], hp[1], hp[2], hp[3]);
            float sq = 0.f;
            #pragma unroll
            for (int k = 0; k < 8; k++) sq += f[k] * f[k];
            sq += __shfl_xor_sync(0xFFFFFFFFu, sq, 1);
            sq += __shfl_xor_sync(0xFFFFFFFFu, sq, 2);
            sq += __shfl_xor_sync(0xFFFFFFFFu, sq, 4);
            if (c == 0) gx2[(size_t)tile * 128 + r] = sq;
        }
    }
}

// ---------------- persistent fused kernel: all 26 iterations ----------------
__global__ void __launch_bounds__(THREADS, 3)
fcm_persist(const float* __restrict__ u0, int N, float* __restrict__ out)
{
    extern __shared__ char smem[];
    const uint32_t sb = smem_u32(smem);
    float* x2s = (float*)(smem + OFF_X2);
    float* c2s = (float*)(smem + OFF_C2);

    const int t = threadIdx.x;
    const int w = t >> 5, lane = t & 31;
    const int quad = lane >> 2, qid = lane & 3;
    const int seg = lane >> 3, q = lane & 7;
    const int nblk = gridDim.x;
    const int ntiles = (N + 127) >> 7;
    const int jm = (w & 3) * 16;        // GEMM2 m-tile (j rows)
    const int nb = (w >> 2) * 4;        // GEMM2 n-tile base (d/8)

    if (blockIdx.x == 0 && t == 0) g_done = 0;

    for (int iter = 0; iter <= 25; iter++) {
        const int mode = (iter > 0);

        float G[4][4];
        #pragma unroll
        for (int a = 0; a < 4; a++)
            #pragma unroll
            for (int b = 0; b < 4; b++) G[a][b] = 0.f;
        float DEN[4] = {0.f, 0.f, 0.f, 0.f};

        // iter 0: stage first tile here; iter>0: staged in previous pass tail
        if (iter == 0 && blockIdx.x < ntiles) stage_tile(blockIdx.x, sb, OFF_XH0, 0, t);

        int buf = 0;
        for (int tile = blockIdx.x; tile < ntiles; tile += nblk) {
            cp_wait0();
            __syncthreads();   // buf's X tile visible; previous GEMM2 reads done

            const uint32_t xhoff = buf ? OFF_XH1 : OFF_XH0;

            // prefetch next tile into the other buffer (overlaps everything below)
            int ntile = tile + nblk;
            if (ntile < ntiles) stage_tile(ntile, sb, buf ? OFF_XH0 : OFF_XH1, buf ^ 1, t);

            // ---- memberships ----
            float S[8][4];
            const int r1l = 16 * w + quad;
            const int grow1 = tile * 128 + r1l;
            const int grow2 = grow1 + 8;

            if (mode) {
                #pragma unroll
                for (int tn = 0; tn < 8; tn++)
                    #pragma unroll
                    for (int b = 0; b < 4; b++) S[tn][b] = 0.f;
                // GEMM1 single chain: S = Xh.Ch^T  (warp w: rows 16w..16w+15)
                #pragma unroll
                for (int kk = 0; kk < 4; kk++) {
                    uint32_t ah[4];
                    ldsm4(ah, sb + xhoff + swz(16 * w + (seg & 1) * 8 + q,
                                               kk * 16 + (seg >> 1) * 8));
                    #pragma unroll
                    for (int tnp = 0; tnp < 4; tnp++) {
                        uint32_t bb[4];
                        ldsm4(bb, sb + OFF_CH + swz(16 * tnp + ((lane >> 4) << 3) + q,
                                                    kk * 16 + ((lane >> 3) & 1) * 8));
                        mma16816(S[2 * tnp],     ah, bb);
                        mma16816(S[2 * tnp + 1], ah, bb + 2);
                    }
                }
                float xx1 = x2s[buf * 128 + r1l], xx2 = x2s[buf * 128 + r1l + 8];
                #pragma unroll
                for (int tn = 0; tn < 8; tn++) {
                    int j = 8 * tn + qid * 2;
                    float ca = c2s[j], cb = c2s[j + 1];
                    S[tn][0] = frcp(fmaxf(xx1 + ca - 2.f * S[tn][0], 0.f));
                    S[tn][1] = frcp(fmaxf(xx1 + cb - 2.f * S[tn][1], 0.f));
                    S[tn][2] = frcp(fmaxf(xx2 + ca - 2.f * S[tn][2], 0.f));
                    S[tn][3] = frcp(fmaxf(xx2 + cb - 2.f * S[tn][3], 0.f));
                }
            } else {
                #pragma unroll
                for (int tn = 0; tn < 8; tn++) {
                    int j = 8 * tn + qid * 2;
                    float2 p1 = make_float2(0.f, 0.f), p2 = p1;
                    if (grow1 < N) p1 = *reinterpret_cast<const float2*>(u0 + (size_t)grow1 * 64 + j);
                    if (grow2 < N) p2 = *reinterpret_cast<const float2*>(u0 + (size_t)grow2 * 64 + j);
                    S[tn][0] = p1.x; S[tn][1] = p1.y; S[tn][2] = p2.x; S[tn][3] = p2.y;
                }
            }

            float s1 = 0.f, s2 = 0.f;
            #pragma unroll
            for (int tn = 0; tn < 8; tn++) { s1 += S[tn][0] + S[tn][1]; s2 += S[tn][2] + S[tn][3]; }
            s1 += __shfl_xor_sync(0xFFFFFFFFu, s1, 1);
            s1 += __shfl_xor_sync(0xFFFFFFFFu, s1, 2);
            s2 += __shfl_xor_sync(0xFFFFFFFFu, s2, 1);
            s2 += __shfl_xor_sync(0xFFFFFFFFu, s2, 2);
            float i1 = (grow1 < N) ? frcp(s1) : 0.f;
            float i2 = (grow2 < N) ? frcp(s2) : 0.f;

            // u^2 -> fp16 (hi only) -> smem U tile
            #pragma unroll
            for (int tn = 0; tn < 8; tn++) {
                int j = 8 * tn + qid * 2;
                float ua0 = S[tn][0] * i1; ua0 *= ua0;
                float ua1 = S[tn][1] * i1; ua1 *= ua1;
                float ub0 = S[tn][2] * i2; ub0 *= ub0;
                float ub1 = S[tn][3] * i2; ub1 *= ub1;
                *(uint32_t*)(smem + OFF_UH + swz(r1l, j)) =
                    packh2(__float2half_rn(ua0), __float2half_rn(ua1));
                *(uint32_t*)(smem + OFF_UH + swz(r1l + 8, j)) =
                    packh2(__float2half_rn(ub0), __float2half_rn(ub1));
            }
            __syncthreads();   // U visible

            // ---- GEMM2 single chain: G += Uh^T Xh ; den += Uh^T ones ----
            {
                const uint32_t ones[2] = {0x3C003C00u, 0x3C003C00u};
                #pragma unroll
                for (int rr = 0; rr < 8; rr++) {
                    int ur = rr * 16 + (seg >> 1) * 8 + q;
                    int uc = jm + (seg & 1) * 8;
                    uint32_t auh[4];
                    ldsm4t(auh, sb + OFF_UH + swz(ur, uc));
                    #pragma unroll
                    for (int tnp = 0; tnp < 2; tnp++) {
                        int d0 = 8 * (nb + 2 * tnp);
                        uint32_t bxh[4];
                        ldsm4t(bxh, sb + xhoff + swz(rr * 16 + ((lane >> 3) & 1) * 8 + q,
                                                     d0 + (lane >> 4) * 8));
                        mma16816(G[2 * tnp],     auh, bxh);
                        mma16816(G[2 * tnp + 1], auh, bxh + 2);
                    }
                    if (w < 4) mma16816(DEN, auh, ones);
                }
            }
            buf ^= 1;
        }
        __syncthreads();   // all warps done with smem buffers

        // prefetch NEXT pass's first tile now (hides load behind barrier/center)
        if (iter < 25 && blockIdx.x < ntiles) stage_tile(blockIdx.x, sb, OFF_XH0, 0, t);

        // ---- flush block partials: plain stores to private slab (no atomics) ----
        {
            float* slab = g_slab[blockIdx.x];
            int j1 = jm + quad;
            #pragma unroll
            for (int tn = 0; tn < 4; tn++) {
                int d = 8 * (nb + tn) + qid * 2;
                *reinterpret_cast<float2*>(slab + j1 * 64 + d)       = make_float2(G[tn][0], G[tn][1]);
                *reinterpret_cast<float2*>(slab + (j1 + 8) * 64 + d) = make_float2(G[tn][2], G[tn][3]);
            }
            if (w < 4 && qid == 0) {
                g_dslab[blockIdx.x][j1]     = DEN[0];
                g_dslab[blockIdx.x][j1 + 8] = DEN[2];
            }
        }

        gridbar(nblk);

        // ---- distributed center: block j reduces cluster row j over all slabs ----
        const int pnew = iter & 1, pold = pnew ^ 1;
        if (blockIdx.x < 64) {
            const int j = blockIdx.x;
            float* sred = (float*)(smem + OFF_UH);          // 256 floats (U region is dead)
            float* sdj  = (float*)(smem + OFF_UH + 1024);
            const int d = t & 63, chunk = t >> 6;
            float acc = 0.f;
            for (int b = chunk; b < nblk; b += 4)
                acc += __ldcg(&g_slab[b][j * 64 + d]);
            sred[t] = acc;
            __syncthreads();
            if (w == 0) {
                float dn = 0.f;
                for (int b = lane; b < nblk; b += 32) dn += __ldcg(&g_dslab[b][j]);
                #pragma unroll
                for (int m = 16; m > 0; m >>= 1) dn += __shfl_xor_sync(0xFFFFFFFFu, dn, m);
                if (lane == 0) sdj[0] = dn;
            }
            __syncthreads();
            if (t < 64) {
                float num = sred[t] + sred[t + 64] + sred[t + 128] + sred[t + 192];
                float c = num / sdj[0];
                g_C[pnew][j * 64 + t] = c;
                if (iter > 0) {
                    float dd = c - __ldcg(&g_C[pold][j * 64 + t]);
                    float s = dd * dd;
                    #pragma unroll
                    for (int m = 16; m > 0; m >>= 1) s += __shfl_xor_sync(0xFFFFFFFFu, s, m);
                    if ((t & 31) == 0) atomicAdd(&g_diff, s);
                }
            }
        }

        gridbar(nblk);

        // ---- convergence latch (block 0; out tracks C_{k-1}, frozen once done) ----
        if (blockIdx.x == 0 && iter > 0) {
            int done = g_done;
            __syncthreads();
            if (!done)
                for (int i = t; i < 4096; i += THREADS) out[i] = __ldcg(&g_C[pold][i]);
            __syncthreads();
            if (t == 0) {
                float df = g_diff;
                if (!done && sqrtf(df) < 1e-8f) g_done = 1;
                g_diff = 0.f;
            }
        }

        // ---- build C tile + c2 for next pass ----
        if (iter < 25) {
            const float* C = g_C[pnew];
            for (int i = t; i < 4096; i += THREADS) {
                int j = i >> 6, d = i & 63;
                *(half*)(smem + OFF_CH + swz(j, d)) = __float2half_rn(__ldcg(&C[i]));
            }
            {
                // c2: thread group of 4 per row, quad shfl reduce
                int j = t >> 2, part = t & 3;
                const float4* Cr = reinterpret_cast<const float4*>(C + j * 64) + part * 4;
                float s = 0.f;
                #pragma unroll
                for (int k = 0; k < 4; k++) {
                    float4 v = Cr[k];
                    s += v.x * v.x + v.y * v.y + v.z * v.z + v.w * v.w;
                }
                s += __shfl_xor_sync(0xFFFFFFFFu, s, 1);
                s += __shfl_xor_sync(0xFFFFFFFFu, s, 2);
                if (part == 0) c2s[j] = s;
            }
            __syncthreads();
        }
    }

    // ---- final: if never converged, answer is C_25 ----
    if (blockIdx.x == 0) {
        __syncthreads();
        if (!g_done)
            for (int i = t; i < 4096; i += THREADS) out[i] = __ldcg(&g_C[1][i]);
    }
}

// ---------------- host launch ----------------
extern "C" void kernel_launch(void* const* d_in, const int* in_sizes, int n_in,
                              void* d_out, int out_size) {
    const float* data = (const float*)d_in[0];
    const float* u0   = (const float*)d_in[1];
    const int N = in_sizes[0] / 64;     // 300000
    float* out = (float*)d_out;
    const int ntiles = (N + 127) >> 7;

    cudaFuncSetAttribute(fcm_persist, cudaFuncAttributeMaxDynamicSharedMemorySize, SMEM_BYTES);

    int nbsm = 0;
    cudaOccupancyMaxActiveBlocksPerMultiprocessor(&nbsm, fcm_persist, THREADS, SMEM_BYTES);
    if (nbsm < 1) nbsm = 1;
    if (nbsm > 3) nbsm = 3;
    int dev = 0, nsm = 148;
    cudaGetDevice(&dev);
    cudaDeviceGetAttribute(&nsm, cudaDevAttrMultiProcessorCount, dev);
    int grid = nbsm * nsm;   // all CTAs co-resident -> software grid barrier is safe
    if (grid > MAXBLK) grid = MAXBLK;

    fcm_pre<<<grid, THREADS>>>(data, N, ntiles);
    fcm_persist<<<grid, THREADS, SMEM_BYTES>>>(u0, N, out);
}

// round 10
// speedup vs baseline: 6.3220x; 1.0783x over previous
#include <cuda_runtime.h>
#include <cuda_fp16.h>
#include <cstdint>

#define THREADS 256
#define MAXTILES 2350   // >= ceil(300000/128)
#define MAXBLK   512

// ---------------- device-global state (no allocations allowed) ----------------
__device__ float g_C[2][64 * 64];
__device__ float g_slab[MAXBLK][64 * 64];   // per-block GEMM2 partials (plain STG)
__device__ float g_dslab[MAXBLK][64];       // per-block den partials
__device__ float g_diff;
__device__ int   g_done;
__device__ unsigned g_bar_cnt;
__device__ volatile unsigned g_bar_gen;

// center-produced artifacts for the next pass
__device__ uint4 gCimg[512];                 // swizzled fp16 C tile image (8 KB)
__device__ __align__(16) float gc2[64];      // exact fp32 row norms of C

// precomputed fp16 X (hi part), per-tile swizzled smem images (16 KB each) + exact norms
__device__ char  gXh[(size_t)MAXTILES * 16384];
__device__ float gx2[(size_t)MAXTILES * 128];

// ---------------- smem layout (bytes) ----------------
#define OFF_XH0   0        // X hi buf0 [128][64] half swizzled, 16 KB
#define OFF_XH1   16384
#define OFF_UH    32768    // U^2 hi [128 r][64 j] half swizzled, 16 KB (reused in center)
#define OFF_CH    49152    // C hi [64][64] half swizzled, 8 KB
#define OFF_X2    57344    // float[2][128]
#define OFF_C2    58368    // float[64]
#define SMEM_BYTES 58624

// XOR swizzle: 16B-chunk permutation within a 128B row (conflict-free ldmatrix)
static __device__ __forceinline__ uint32_t swz(int r, int colhalf) {
    return (uint32_t)(r * 128 + ((colhalf * 2) ^ ((r & 7) << 4)));
}
static __device__ __forceinline__ uint32_t smem_u32(const void* p) {
    uint32_t a;
    asm("{ .reg .u64 t; cvta.to.shared.u64 t, %1; cvt.u32.u64 %0, t; }" : "=r"(a) : "l"(p));
    return a;
}
static __device__ __forceinline__ float frcp(float x) {
    float y;
    asm("rcp.approx.f32 %0, %1;" : "=f"(y) : "f"(x));
    return y;
}

// ---------------- cp.async ----------------
static __device__ __forceinline__ void cp_async16(uint32_t dst, const void* src) {
    asm volatile("cp.async.cg.shared.global [%0], [%1], 16;"
                 :: "r"(dst), "l"(src) : "memory");
}
static __device__ __forceinline__ void cp_commit() {
    asm volatile("cp.async.commit_group;" ::: "memory");
}
static __device__ __forceinline__ void cp_wait0() {
    asm volatile("cp.async.wait_group 0;" ::: "memory");
}

// ---------------- mma / ldmatrix wrappers ----------------
static __device__ __forceinline__ void ldsm4(uint32_t* r, uint32_t a) {
    asm volatile("ldmatrix.sync.aligned.m8n8.x4.shared.b16 {%0,%1,%2,%3}, [%4];"
                 : "=r"(r[0]), "=r"(r[1]), "=r"(r[2]), "=r"(r[3]) : "r"(a));
}
static __device__ __forceinline__ void ldsm4t(uint32_t* r, uint32_t a) {
    asm volatile("ldmatrix.sync.aligned.m8n8.x4.trans.shared.b16 {%0,%1,%2,%3}, [%4];"
                 : "=r"(r[0]), "=r"(r[1]), "=r"(r[2]), "=r"(r[3]) : "r"(a));
}
static __device__ __forceinline__ void mma16816(float* d, const uint32_t* a, const uint32_t* b) {
    asm volatile("mma.sync.aligned.m16n8k16.row.col.f32.f16.f16.f32 "
                 "{%0,%1,%2,%3}, {%4,%5,%6,%7}, {%8,%9}, {%0,%1,%2,%3};"
                 : "+f"(d[0]), "+f"(d[1]), "+f"(d[2]), "+f"(d[3])
                 : "r"(a[0]), "r"(a[1]), "r"(a[2]), "r"(a[3]), "r"(b[0]), "r"(b[1]));
}
static __device__ __forceinline__ uint32_t packh2(half a, half b) {
    half2 h = __halves2half2(a, b);
    return *reinterpret_cast<uint32_t*>(&h);
}

// stage one precomputed tile (Xh image + x2 row) into an smem buffer
static __device__ __forceinline__ void stage_tile(int tile, uint32_t sb,
                                                  uint32_t xhoff, int x2slot, int t) {
    const char* srcH = gXh + (size_t)tile * 16384;
    #pragma unroll
    for (int k = 0; k < 4; k++) {
        int c = t + k * THREADS;          // 16B chunk id, 0..1023
        cp_async16(sb + xhoff + c * 16, srcH + c * 16);
    }
    if (t < 32) cp_async16(sb + OFF_X2 + x2slot * 512 + t * 16,
                           (const char*)(gx2 + (size_t)tile * 128) + t * 16);
    cp_commit();
}

// software grid barrier (all CTAs co-resident; grid sized by occupancy)
static __device__ __forceinline__ void gridbar(int nblk) {
    __syncthreads();
    if (threadIdx.x == 0) {
        unsigned gen = g_bar_gen;
        __threadfence();
        if (atomicAdd(&g_bar_cnt, 1u) == (unsigned)nblk - 1u) {
            g_bar_cnt = 0;
            __threadfence();
            g_bar_gen = gen + 1u;
        } else {
            while (g_bar_gen == gen) { __nanosleep(64); }
        }
    }
    __syncthreads();
}

// ---------------- one-shot precompute: fp32 -> swizzled fp16 hi + exact norms ----
__global__ void __launch_bounds__(THREADS)
fcm_pre(const float* __restrict__ data, int N, int ntiles)
{
    const int t = threadIdx.x;
    for (int tile = blockIdx.x; tile < ntiles; tile += gridDim.x) {
        char* dstH = gXh + (size_t)tile * 16384;
        #pragma unroll
        for (int it = 0; it < 4; it++) {
            int i = t + it * THREADS;      // 0..1023
            int r = i >> 3, c = i & 7;     // row, 8-float chunk
            int grow = tile * 128 + r;
            float4 v0 = make_float4(0.f, 0.f, 0.f, 0.f), v1 = v0;
            if (grow < N) {
                const float4* p = reinterpret_cast<const float4*>(data + (size_t)grow * 64 + c * 8);
                v0 = p[0]; v1 = p[1];
            }
            float f[8] = {v0.x, v0.y, v0.z, v0.w, v1.x, v1.y, v1.z, v1.w};
            uint32_t hp[4];
            #pragma unroll
            for (int k = 0; k < 4; k++)
                hp[k] = packh2(__float2half_rn(f[2*k]), __float2half_rn(f[2*k+1]));
            *reinterpret_cast<uint4*>(dstH + swz(r, c * 8)) = make_uint4(hp[0], hp[1], hp[2], hp[3]);
            float sq = 0.f;
            #pragma unroll
            for (int k = 0; k < 8; k++) sq += f[k] * f[k];
            sq += __shfl_xor_sync(0xFFFFFFFFu, sq, 1);
            sq += __shfl_xor_sync(0xFFFFFFFFu, sq, 2);
            sq += __shfl_xor_sync(0xFFFFFFFFu, sq, 4);
            if (c == 0) gx2[(size_t)tile * 128 + r] = sq;
        }
    }
}

// ---------------- persistent fused kernel: all 26 iterations ----------------
__global__ void __launch_bounds__(THREADS, 3)
fcm_persist(const float* __restrict__ u0, int N, float* __restrict__ out)
{
    extern __shared__ char smem[];
    const uint32_t sb = smem_u32(smem);
    float* x2s = (float*)(smem + OFF_X2);
    float* c2s = (float*)(smem + OFF_C2);

    const int t = threadIdx.x;
    const int w = t >> 5, lane = t & 31;
    const int quad = lane >> 2, qid = lane & 3;
    const int seg = lane >> 3, q = lane & 7;
    const int nblk = gridDim.x;
    const int ntiles = (N + 127) >> 7;
    const int jm = (w & 3) * 16;        // GEMM2 m-tile (j rows)
    const int nb = (w >> 2) * 4;        // GEMM2 n-tile base (d/8)

    if (blockIdx.x == 0 && t == 0) g_done = 0;

    for (int iter = 0; iter <= 25; iter++) {
        const int mode = (iter > 0);

        float G[4][4];
        #pragma unroll
        for (int a = 0; a < 4; a++)
            #pragma unroll
            for (int b = 0; b < 4; b++) G[a][b] = 0.f;
        float DEN[4] = {0.f, 0.f, 0.f, 0.f};

        // iter 0: stage first tile here; iter>0: staged in previous pass tail
        if (iter == 0 && blockIdx.x < ntiles) stage_tile(blockIdx.x, sb, OFF_XH0, 0, t);

        int buf = 0;
        for (int tile = blockIdx.x; tile < ntiles; tile += nblk) {
            cp_wait0();
            __syncthreads();   // buf's X tile (+ C image on first tile) visible

            const uint32_t xhoff = buf ? OFF_XH1 : OFF_XH0;

            // prefetch next tile into the other buffer (overlaps everything below)
            int ntile = tile + nblk;
            if (ntile < ntiles) stage_tile(ntile, sb, buf ? OFF_XH0 : OFF_XH1, buf ^ 1, t);

            // ---- memberships ----
            float S[8][4];
            const int r1l = 16 * w + quad;
            const int grow1 = tile * 128 + r1l;
            const int grow2 = grow1 + 8;

            if (mode) {
                #pragma unroll
                for (int tn = 0; tn < 8; tn++)
                    #pragma unroll
                    for (int b = 0; b < 4; b++) S[tn][b] = 0.f;
                // GEMM1 single chain: S = Xh.Ch^T  (warp w: rows 16w..16w+15)
                #pragma unroll
                for (int kk = 0; kk < 4; kk++) {
                    uint32_t ah[4];
                    ldsm4(ah, sb + xhoff + swz(16 * w + (seg & 1) * 8 + q,
                                               kk * 16 + (seg >> 1) * 8));
                    #pragma unroll
                    for (int tnp = 0; tnp < 4; tnp++) {
                        uint32_t bb[4];
                        ldsm4(bb, sb + OFF_CH + swz(16 * tnp + ((lane >> 4) << 3) + q,
                                                    kk * 16 + ((lane >> 3) & 1) * 8));
                        mma16816(S[2 * tnp],     ah, bb);
                        mma16816(S[2 * tnp + 1], ah, bb + 2);
                    }
                }
                float xx1 = x2s[buf * 128 + r1l], xx2 = x2s[buf * 128 + r1l + 8];
                #pragma unroll
                for (int tn = 0; tn < 8; tn++) {
                    int j = 8 * tn + qid * 2;
                    float ca = c2s[j], cb = c2s[j + 1];
                    S[tn][0] = frcp(fmaxf(xx1 + ca - 2.f * S[tn][0], 0.f));
                    S[tn][1] = frcp(fmaxf(xx1 + cb - 2.f * S[tn][1], 0.f));
                    S[tn][2] = frcp(fmaxf(xx2 + ca - 2.f * S[tn][2], 0.f));
                    S[tn][3] = frcp(fmaxf(xx2 + cb - 2.f * S[tn][3], 0.f));
                }
            } else {
                #pragma unroll
                for (int tn = 0; tn < 8; tn++) {
                    int j = 8 * tn + qid * 2;
                    float2 p1 = make_float2(0.f, 0.f), p2 = p1;
                    if (grow1 < N) p1 = *reinterpret_cast<const float2*>(u0 + (size_t)grow1 * 64 + j);
                    if (grow2 < N) p2 = *reinterpret_cast<const float2*>(u0 + (size_t)grow2 * 64 + j);
                    S[tn][0] = p1.x; S[tn][1] = p1.y; S[tn][2] = p2.x; S[tn][3] = p2.y;
                }
            }

            float s1 = 0.f, s2 = 0.f;
            #pragma unroll
            for (int tn = 0; tn < 8; tn++) { s1 += S[tn][0] + S[tn][1]; s2 += S[tn][2] + S[tn][3]; }
            s1 += __shfl_xor_sync(0xFFFFFFFFu, s1, 1);
            s1 += __shfl_xor_sync(0xFFFFFFFFu, s1, 2);
            s2 += __shfl_xor_sync(0xFFFFFFFFu, s2, 1);
            s2 += __shfl_xor_sync(0xFFFFFFFFu, s2, 2);
            float i1 = (grow1 < N) ? frcp(s1) : 0.f;
            float i2 = (grow2 < N) ? frcp(s2) : 0.f;

            // u -> half2, u^2 via HMUL2 -> smem U tile
            #pragma unroll
            for (int tn = 0; tn < 8; tn++) {
                int j = 8 * tn + qid * 2;
                half2 ha = __floats2half2_rn(S[tn][0] * i1, S[tn][1] * i1);
                half2 hb = __floats2half2_rn(S[tn][2] * i2, S[tn][3] * i2);
                ha = __hmul2(ha, ha);
                hb = __hmul2(hb, hb);
                *(uint32_t*)(smem + OFF_UH + swz(r1l, j))     = *reinterpret_cast<uint32_t*>(&ha);
                *(uint32_t*)(smem + OFF_UH + swz(r1l + 8, j)) = *reinterpret_cast<uint32_t*>(&hb);
            }
            __syncthreads();   // U visible

            // ---- GEMM2 single chain: G += Uh^T Xh ; den += Uh^T ones ----
            {
                const uint32_t ones[2] = {0x3C003C00u, 0x3C003C00u};
                #pragma unroll
                for (int rr = 0; rr < 8; rr++) {
                    int ur = rr * 16 + (seg >> 1) * 8 + q;
                    int uc = jm + (seg & 1) * 8;
                    uint32_t auh[4];
                    ldsm4t(auh, sb + OFF_UH + swz(ur, uc));
                    #pragma unroll
                    for (int tnp = 0; tnp < 2; tnp++) {
                        int d0 = 8 * (nb + 2 * tnp);
                        uint32_t bxh[4];
                        ldsm4t(bxh, sb + xhoff + swz(rr * 16 + ((lane >> 3) & 1) * 8 + q,
                                                     d0 + (lane >> 4) * 8));
                        mma16816(G[2 * tnp],     auh, bxh);
                        mma16816(G[2 * tnp + 1], auh, bxh + 2);
                    }
                    if (w < 4) mma16816(DEN, auh, ones);
                }
            }
            buf ^= 1;
        }
        __syncthreads();   // all warps done with smem buffers

        // prefetch NEXT pass's first tile now (hides load behind barrier/center)
        if (iter < 25 && blockIdx.x < ntiles) stage_tile(blockIdx.x, sb, OFF_XH0, 0, t);

        // ---- flush block partials: plain stores to private slab (no atomics) ----
        {
            float* slab = g_slab[blockIdx.x];
            int j1 = jm + quad;
            #pragma unroll
            for (int tn = 0; tn < 4; tn++) {
                int d = 8 * (nb + tn) + qid * 2;
                *reinterpret_cast<float2*>(slab + j1 * 64 + d)       = make_float2(G[tn][0], G[tn][1]);
                *reinterpret_cast<float2*>(slab + (j1 + 8) * 64 + d) = make_float2(G[tn][2], G[tn][3]);
            }
            if (w < 4 && qid == 0) {
                g_dslab[blockIdx.x][j1]     = DEN[0];
                g_dslab[blockIdx.x][j1 + 8] = DEN[2];
            }
        }

        gridbar(nblk);

        // ---- distributed center: block j reduces row j, emits C/image/c2/out ----
        const int pnew = iter & 1, pold = pnew ^ 1;
        if (blockIdx.x < 64) {
            const int j = blockIdx.x;
            float* sred = (float*)(smem + OFF_UH);          // U region is dead here
            float* sdj  = (float*)(smem + OFF_UH + 1024);
            float* crow = (float*)(smem + OFF_UH + 1088);
            const int d = t & 63, chunk = t >> 6;
            float acc = 0.f;
            for (int b = chunk; b < nblk; b += 4)
                acc += __ldcg(&g_slab[b][j * 64 + d]);
            sred[t] = acc;
            __syncthreads();
            if (w == 0) {
                float dn = 0.f;
                for (int b = lane; b < nblk; b += 32) dn += __ldcg(&g_dslab[b][j]);
                #pragma unroll
                for (int m = 16; m > 0; m >>= 1) dn += __shfl_xor_sync(0xFFFFFFFFu, dn, m);
                if (lane == 0) sdj[0] = dn;
            }
            __syncthreads();
            if (t < 64) {
                float num = sred[t] + sred[t + 64] + sred[t + 128] + sred[t + 192];
                float c = num / sdj[0];
                g_C[pnew][j * 64 + t] = c;
                crow[t] = c;
                if (iter > 0) {
                    float pv = __ldcg(&g_C[pold][j * 64 + t]);
                    float dd = c - pv;
                    float s = dd * dd;
                    #pragma unroll
                    for (int m = 16; m > 0; m >>= 1) s += __shfl_xor_sync(0xFFFFFFFFu, s, m);
                    if ((t & 31) == 0) atomicAdd(&g_diff, s);
                    if (!g_done) out[j * 64 + t] = pv;   // out tracks C_{k-1}; frozen once done
                }
            }
            __syncthreads();
            if (w == 0) {
                // swizzled fp16 image of row j (lane<32 packs pairs)
                uint32_t pk = packh2(__float2half_rn(crow[2 * lane]),
                                     __float2half_rn(crow[2 * lane + 1]));
                *(uint32_t*)((char*)gCimg + swz(j, 2 * lane)) = pk;
                // exact c2[j]
                float v0 = crow[lane], v1 = crow[lane + 32];
                float s = v0 * v0 + v1 * v1;
                #pragma unroll
                for (int m = 16; m > 0; m >>= 1) s += __shfl_xor_sync(0xFFFFFFFFu, s, m);
                if (lane == 0) gc2[j] = s;
            }
        }

        gridbar(nblk);

        // ---- latch update (block 0 only; g_diff holds ||C_k - C_{k-1}||^2) ----
        if (blockIdx.x == 0 && t == 0 && iter > 0) {
            float df = g_diff;
            if (!g_done && sqrtf(df) < 1e-8f) g_done = 1;
            g_diff = 0.f;
        }

        // ---- load next pass's C image + c2 (consumed at first-tile cp_wait0) ----
        if (iter < 25) {
            #pragma unroll
            for (int k = 0; k < 2; k++) {
                int c = t + k * THREADS;   // 0..511 chunks of 16B
                cp_async16(sb + OFF_CH + c * 16, (const char*)gCimg + c * 16);
            }
            if (t < 16) cp_async16(sb + OFF_C2 + t * 16, (const char*)gc2 + t * 16);
            cp_commit();
        }
    }

    // ---- final: if never converged, answer is C_25 ----
    if (blockIdx.x == 0) {
        __syncthreads();   // t0's g_done update visible to whole block
        if (!g_done)
            for (int i = t; i < 4096; i += THREADS) out[i] = __ldcg(&g_C[1][i]);
    }
}

// ---------------- host launch ----------------
extern "C" void kernel_launch(void* const* d_in, const int* in_sizes, int n_in,
                              void* d_out, int out_size) {
    const float* data = (const float*)d_in[0];
    const float* u0   = (const float*)d_in[1];
    const int N = in_sizes[0] / 64;     // 300000
    float* out = (float*)d_out;
    const int ntiles = (N + 127) >> 7;

    cudaFuncSetAttribute(fcm_persist, cudaFuncAttributeMaxDynamicSharedMemorySize, SMEM_BYTES);

    int nbsm = 0;
    cudaOccupancyMaxActiveBlocksPerMultiprocessor(&nbsm, fcm_persist, THREADS, SMEM_BYTES);
    if (nbsm < 1) nbsm = 1;
    if (nbsm > 3) nbsm = 3;
    int dev = 0, nsm = 148;
    cudaGetDevice(&dev);
    cudaDeviceGetAttribute(&nsm, cudaDevAttrMultiProcessorCount, dev);
    int grid = nbsm * nsm;   // all CTAs co-resident -> software grid barrier is safe
    if (grid > MAXBLK) grid = MAXBLK;

    fcm_pre<<<grid, THREADS>>>(data, N, ntiles);
    fcm_persist<<<grid, THREADS, SMEM_BYTES>>>(u0, N, out);
}

// round 11
// speedup vs baseline: 6.8262x; 1.0797x over previous
#include <cuda_runtime.h>
#include <cuda_fp16.h>
#include <cstdint>

#define THREADS 256
#define MAXTILES 2350   // >= ceil(300000/128)
#define MAXBLK   512

// ---------------- device-global state (no allocations allowed) ----------------
__device__ float g_C[2][64 * 64];
__device__ float g_slab[MAXBLK][64 * 64];   // per-block GEMM2 partials (plain STG)
__device__ float g_dslab[MAXBLK][64];       // per-block den partials
__device__ float g_diff;
__device__ int   g_done;
__device__ unsigned g_bar_cnt;
__device__ volatile unsigned g_bar_gen;

// center-produced artifacts for the next pass
__device__ uint4 gCimg[512];                 // swizzled fp16 C tile image (8 KB)
__device__ __align__(16) float gc2[64];      // exact fp32 row norms of C

// precomputed fp16 X (hi part), per-tile swizzled smem images (16 KB each) + exact norms
__device__ char  gXh[(size_t)MAXTILES * 16384];
__device__ float gx2[(size_t)MAXTILES * 128];

// ---------------- smem layout (bytes) ----------------
#define OFF_XH0   0        // X hi buf0 [128][64] half swizzled, 16 KB
#define OFF_XH1   16384
#define OFF_UH    32768    // U^2 hi [128 r][64 j] half swizzled, 16 KB (reused in center)
#define OFF_CH    49152    // C hi [64][64] half swizzled, 8 KB
#define OFF_X2    57344    // float[2][128]
#define OFF_C2    58368    // float[64]
#define SMEM_BYTES 58624

// XOR swizzle: 16B-chunk permutation within a 128B row (conflict-free ldmatrix)
static __device__ __forceinline__ uint32_t swz(int r, int colhalf) {
    return (uint32_t)(r * 128 + ((colhalf * 2) ^ ((r & 7) << 4)));
}
static __device__ __forceinline__ uint32_t smem_u32(const void* p) {
    uint32_t a;
    asm("{ .reg .u64 t; cvta.to.shared.u64 t, %1; cvt.u32.u64 %0, t; }" : "=r"(a) : "l"(p));
    return a;
}
static __device__ __forceinline__ float frcp(float x) {
    float y;
    asm("rcp.approx.f32 %0, %1;" : "=f"(y) : "f"(x));
    return y;
}

// ---------------- cp.async ----------------
static __device__ __forceinline__ void cp_async16(uint32_t dst, const void* src) {
    asm volatile("cp.async.cg.shared.global [%0], [%1], 16;"
                 :: "r"(dst), "l"(src) : "memory");
}
static __device__ __forceinline__ void cp_commit() {
    asm volatile("cp.async.commit_group;" ::: "memory");
}
static __device__ __forceinline__ void cp_wait0() {
    asm volatile("cp.async.wait_group 0;" ::: "memory");
}

// ---------------- mma / ldmatrix wrappers ----------------
static __device__ __forceinline__ void ldsm4(uint32_t* r, uint32_t a) {
    asm volatile("ldmatrix.sync.aligned.m8n8.x4.shared.b16 {%0,%1,%2,%3}, [%4];"
                 : "=r"(r[0]), "=r"(r[1]), "=r"(r[2]), "=r"(r[3]) : "r"(a));
}
static __device__ __forceinline__ void ldsm4t(uint32_t* r, uint32_t a) {
    asm volatile("ldmatrix.sync.aligned.m8n8.x4.trans.shared.b16 {%0,%1,%2,%3}, [%4];"
                 : "=r"(r[0]), "=r"(r[1]), "=r"(r[2]), "=r"(r[3]) : "r"(a));
}
static __device__ __forceinline__ void mma16816(float* d, const uint32_t* a, const uint32_t* b) {
    asm volatile("mma.sync.aligned.m16n8k16.row.col.f32.f16.f16.f32 "
                 "{%0,%1,%2,%3}, {%4,%5,%6,%7}, {%8,%9}, {%0,%1,%2,%3};"
                 : "+f"(d[0]), "+f"(d[1]), "+f"(d[2]), "+f"(d[3])
                 : "r"(a[0]), "r"(a[1]), "r"(a[2]), "r"(a[3]), "r"(b[0]), "r"(b[1]));
}
static __device__ __forceinline__ uint32_t packh2(half a, half b) {
    half2 h = __halves2half2(a, b);
    return *reinterpret_cast<uint32_t*>(&h);
}

// stage one precomputed tile (Xh image + x2 row) into an smem buffer
static __device__ __forceinline__ void stage_tile(int tile, uint32_t sb,
                                                  uint32_t xhoff, int x2slot, int t) {
    const char* srcH = gXh + (size_t)tile * 16384;
    #pragma unroll
    for (int k = 0; k < 4; k++) {
        int c = t + k * THREADS;          // 16B chunk id, 0..1023
        cp_async16(sb + xhoff + c * 16, srcH + c * 16);
    }
    if (t < 32) cp_async16(sb + OFF_X2 + x2slot * 512 + t * 16,
                           (const char*)(gx2 + (size_t)tile * 128) + t * 16);
    cp_commit();
}

// software grid barrier (all CTAs co-resident; grid sized by occupancy)
static __device__ __forceinline__ void gridbar(int nblk) {
    __syncthreads();
    if (threadIdx.x == 0) {
        unsigned gen = g_bar_gen;
        __threadfence();
        if (atomicAdd(&g_bar_cnt, 1u) == (unsigned)nblk - 1u) {
            g_bar_cnt = 0;
            __threadfence();
            g_bar_gen = gen + 1u;
        } else {
            while (g_bar_gen == gen) { __nanosleep(64); }
        }
    }
    __syncthreads();
}

// ---------------- one-shot precompute: fp32 -> swizzled fp16 hi + exact norms ----
__global__ void __launch_bounds__(THREADS)
fcm_pre(const float* __restrict__ data, int N, int ntiles)
{
    const int t = threadIdx.x;
    for (int tile = blockIdx.x; tile < ntiles; tile += gridDim.x) {
        char* dstH = gXh + (size_t)tile * 16384;
        #pragma unroll
        for (int it = 0; it < 4; it++) {
            int i = t + it * THREADS;      // 0..1023
            int r = i >> 3, c = i & 7;     // row, 8-float chunk
            int grow = tile * 128 + r;
            float4 v0 = make_float4(0.f, 0.f, 0.f, 0.f), v1 = v0;
            if (grow < N) {
                const float4* p = reinterpret_cast<const float4*>(data + (size_t)grow * 64 + c * 8);
                v0 = p[0]; v1 = p[1];
            }
            float f[8] = {v0.x, v0.y, v0.z, v0.w, v1.x, v1.y, v1.z, v1.w};
            uint32_t hp[4];
            #pragma unroll
            for (int k = 0; k < 4; k++)
                hp[k] = packh2(__float2half_rn(f[2*k]), __float2half_rn(f[2*k+1]));
            *reinterpret_cast<uint4*>(dstH + swz(r, c * 8)) = make_uint4(hp[0], hp[1], hp[2], hp[3]);
            float sq = 0.f;
            #pragma unroll
            for (int k = 0; k < 8; k++) sq += f[k] * f[k];
            sq += __shfl_xor_sync(0xFFFFFFFFu, sq, 1);
            sq += __shfl_xor_sync(0xFFFFFFFFu, sq, 2);
            sq += __shfl_xor_sync(0xFFFFFFFFu, sq, 4);
            if (c == 0) gx2[(size_t)tile * 128 + r] = sq;
        }
    }
}

// ---------------- persistent fused kernel: all 26 iterations ----------------
__global__ void __launch_bounds__(THREADS, 3)
fcm_persist(const float* __restrict__ u0, int N, float* __restrict__ out)
{
    extern __shared__ char smem[];
    const uint32_t sb = smem_u32(smem);
    float* x2s = (float*)(smem + OFF_X2);
    float* c2s = (float*)(smem + OFF_C2);

    const int t = threadIdx.x;
    const int w = t >> 5, lane = t & 31;
    const int quad = lane >> 2, qid = lane & 3;
    const int seg = lane >> 3, q = lane & 7;
    const int nblk = gridDim.x;
    const int ntiles = (N + 127) >> 7;
    const int jm = (w & 3) * 16;        // GEMM2 m-tile (j rows)
    const int nb = (w >> 2) * 4;        // GEMM2 n-tile base (d/8)

    if (blockIdx.x == 0 && t == 0) g_done = 0;

    for (int iter = 0; iter <= 25; iter++) {
        const int mode = (iter > 0);

        float G[4][4];
        #pragma unroll
        for (int a = 0; a < 4; a++)
            #pragma unroll
            for (int b = 0; b < 4; b++) G[a][b] = 0.f;
        float DEN[4] = {0.f, 0.f, 0.f, 0.f};

        // iter 0: stage first tile here; iter>0: staged in previous pass tail
        if (iter == 0 && blockIdx.x < ntiles) stage_tile(blockIdx.x, sb, OFF_XH0, 0, t);

        int buf = 0;
        for (int tile = blockIdx.x; tile < ntiles; tile += nblk) {
            cp_wait0();
            __syncthreads();   // buf's X tile (+ C image on first tile) visible

            const uint32_t xhoff = buf ? OFF_XH1 : OFF_XH0;

            // prefetch next tile into the other buffer (overlaps everything below)
            int ntile = tile + nblk;
            if (ntile < ntiles) stage_tile(ntile, sb, buf ? OFF_XH0 : OFF_XH1, buf ^ 1, t);

            // ---- memberships ----
            float S[8][4];
            const int r1l = 16 * w + quad;
            const int grow1 = tile * 128 + r1l;
            const int grow2 = grow1 + 8;

            if (mode) {
                #pragma unroll
                for (int tn = 0; tn < 8; tn++)
                    #pragma unroll
                    for (int b = 0; b < 4; b++) S[tn][b] = 0.f;
                // GEMM1 single chain: S = Xh.Ch^T  (warp w: rows 16w..16w+15)
                #pragma unroll
                for (int kk = 0; kk < 4; kk++) {
                    uint32_t ah[4];
                    ldsm4(ah, sb + xhoff + swz(16 * w + (seg & 1) * 8 + q,
                                               kk * 16 + (seg >> 1) * 8));
                    #pragma unroll
                    for (int tnp = 0; tnp < 4; tnp++) {
                        uint32_t bb[4];
                        ldsm4(bb, sb + OFF_CH + swz(16 * tnp + ((lane >> 4) << 3) + q,
                                                    kk * 16 + ((lane >> 3) & 1) * 8));
                        mma16816(S[2 * tnp],     ah, bb);
                        mma16816(S[2 * tnp + 1], ah, bb + 2);
                    }
                }
                float xx1 = x2s[buf * 128 + r1l], xx2 = x2s[buf * 128 + r1l + 8];
                // w = 1/dist via pairwise reciprocal: 2 rcp per tn instead of 4
                #pragma unroll
                for (int tn = 0; tn < 8; tn++) {
                    int j = 8 * tn + qid * 2;
                    float2 cc = *reinterpret_cast<const float2*>(&c2s[j]);
                    float d0 = fmaxf(xx1 + cc.x - 2.f * S[tn][0], 0.f);
                    float d1 = fmaxf(xx1 + cc.y - 2.f * S[tn][1], 0.f);
                    float d2 = fmaxf(xx2 + cc.x - 2.f * S[tn][2], 0.f);
                    float d3 = fmaxf(xx2 + cc.y - 2.f * S[tn][3], 0.f);
                    float r01 = frcp(d0 * d1);
                    float r23 = frcp(d2 * d3);
                    S[tn][0] = d1 * r01;
                    S[tn][1] = d0 * r01;
                    S[tn][2] = d3 * r23;
                    S[tn][3] = d2 * r23;
                }
            } else {
                #pragma unroll
                for (int tn = 0; tn < 8; tn++) {
                    int j = 8 * tn + qid * 2;
                    float2 p1 = make_float2(0.f, 0.f), p2 = p1;
                    if (grow1 < N) p1 = *reinterpret_cast<const float2*>(u0 + (size_t)grow1 * 64 + j);
                    if (grow2 < N) p2 = *reinterpret_cast<const float2*>(u0 + (size_t)grow2 * 64 + j);
                    S[tn][0] = p1.x; S[tn][1] = p1.y; S[tn][2] = p2.x; S[tn][3] = p2.y;
                }
            }

            float s1 = 0.f, s2 = 0.f;
            #pragma unroll
            for (int tn = 0; tn < 8; tn++) { s1 += S[tn][0] + S[tn][1]; s2 += S[tn][2] + S[tn][3]; }
            s1 += __shfl_xor_sync(0xFFFFFFFFu, s1, 1);
            s1 += __shfl_xor_sync(0xFFFFFFFFu, s1, 2);
            s2 += __shfl_xor_sync(0xFFFFFFFFu, s2, 1);
            s2 += __shfl_xor_sync(0xFFFFFFFFu, s2, 2);
            // pairwise reciprocal for the two row-sum inverses (sums always > 0)
            float rs = frcp(s1 * s2);
            float i1 = (grow1 < N) ? s2 * rs : 0.f;
            float i2 = (grow2 < N) ? s1 * rs : 0.f;

            // u -> half2, u^2 via HMUL2 -> smem U tile
            #pragma unroll
            for (int tn = 0; tn < 8; tn++) {
                int j = 8 * tn + qid * 2;
                half2 ha = __floats2half2_rn(S[tn][0] * i1, S[tn][1] * i1);
                half2 hb = __floats2half2_rn(S[tn][2] * i2, S[tn][3] * i2);
                ha = __hmul2(ha, ha);
                hb = __hmul2(hb, hb);
                *(uint32_t*)(smem + OFF_UH + swz(r1l, j))     = *reinterpret_cast<uint32_t*>(&ha);
                *(uint32_t*)(smem + OFF_UH + swz(r1l + 8, j)) = *reinterpret_cast<uint32_t*>(&hb);
            }
            __syncthreads();   // U visible

            // ---- GEMM2 single chain: G += Uh^T Xh ; den += Uh^T ones ----
            {
                const uint32_t ones[2] = {0x3C003C00u, 0x3C003C00u};
                #pragma unroll
                for (int rr = 0; rr < 8; rr++) {
                    int ur = rr * 16 + (seg >> 1) * 8 + q;
                    int uc = jm + (seg & 1) * 8;
                    uint32_t auh[4];
                    ldsm4t(auh, sb + OFF_UH + swz(ur, uc));
                    #pragma unroll
                    for (int tnp = 0; tnp < 2; tnp++) {
                        int d0 = 8 * (nb + 2 * tnp);
                        uint32_t bxh[4];
                        ldsm4t(bxh, sb + xhoff + swz(rr * 16 + ((lane >> 3) & 1) * 8 + q,
                                                     d0 + (lane >> 4) * 8));
                        mma16816(G[2 * tnp],     auh, bxh);
                        mma16816(G[2 * tnp + 1], auh, bxh + 2);
                    }
                    if (w < 4) mma16816(DEN, auh, ones);
                }
            }
            buf ^= 1;
        }
        __syncthreads();   // all warps done with smem buffers

        // prefetch NEXT pass's first tile now (hides load behind barrier/center)
        if (iter < 25 && blockIdx.x < ntiles) stage_tile(blockIdx.x, sb, OFF_XH0, 0, t);

        // ---- flush block partials: plain stores to private slab (no atomics) ----
        {
            float* slab = g_slab[blockIdx.x];
            int j1 = jm + quad;
            #pragma unroll
            for (int tn = 0; tn < 4; tn++) {
                int d = 8 * (nb + tn) + qid * 2;
                *reinterpret_cast<float2*>(slab + j1 * 64 + d)       = make_float2(G[tn][0], G[tn][1]);
                *reinterpret_cast<float2*>(slab + (j1 + 8) * 64 + d) = make_float2(G[tn][2], G[tn][3]);
            }
            if (w < 4 && qid == 0) {
                g_dslab[blockIdx.x][j1]     = DEN[0];
                g_dslab[blockIdx.x][j1 + 8] = DEN[2];
            }
        }

        gridbar(nblk);

        // ---- distributed center: block j reduces row j, emits C/image/c2/out ----
        const int pnew = iter & 1, pold = pnew ^ 1;
        if (blockIdx.x < 64) {
            const int j = blockIdx.x;
            float* sred = (float*)(smem + OFF_UH);          // U region is dead here
            float* sdj  = (float*)(smem + OFF_UH + 1024);
            float* crow = (float*)(smem + OFF_UH + 1088);
            const int d = t & 63, chunk = t >> 6;
            float acc = 0.f;
            for (int b = chunk; b < nblk; b += 4)
                acc += __ldcg(&g_slab[b][j * 64 + d]);
            sred[t] = acc;
            __syncthreads();
            if (w == 0) {
                float dn = 0.f;
                for (int b = lane; b < nblk; b += 32) dn += __ldcg(&g_dslab[b][j]);
                #pragma unroll
                for (int m = 16; m > 0; m >>= 1) dn += __shfl_xor_sync(0xFFFFFFFFu, dn, m);
                if (lane == 0) sdj[0] = dn;
            }
            __syncthreads();
            if (t < 64) {
                float num = sred[t] + sred[t + 64] + sred[t + 128] + sred[t + 192];
                float c = num / sdj[0];
                g_C[pnew][j * 64 + t] = c;
                crow[t] = c;
                if (iter > 0) {
                    float pv = __ldcg(&g_C[pold][j * 64 + t]);
                    float dd = c - pv;
                    float s = dd * dd;
                    #pragma unroll
                    for (int m = 16; m > 0; m >>= 1) s += __shfl_xor_sync(0xFFFFFFFFu, s, m);
                    if ((t & 31) == 0) atomicAdd(&g_diff, s);
                    if (!g_done) out[j * 64 + t] = pv;   // out tracks C_{k-1}; frozen once done
                }
            }
            __syncthreads();
            if (w == 0) {
                // swizzled fp16 image of row j (lane<32 packs pairs)
                uint32_t pk = packh2(__float2half_rn(crow[2 * lane]),
                                     __float2half_rn(crow[2 * lane + 1]));
                *(uint32_t*)((char*)gCimg + swz(j, 2 * lane)) = pk;
                // exact c2[j]
                float v0 = crow[lane], v1 = crow[lane + 32];
                float s = v0 * v0 + v1 * v1;
                #pragma unroll
                for (int m = 16; m > 0; m >>= 1) s += __shfl_xor_sync(0xFFFFFFFFu, s, m);
                if (lane == 0) gc2[j] = s;
            }
        }

        gridbar(nblk);

        // ---- latch update (block 0 only; g_diff holds ||C_k - C_{k-1}||^2) ----
        if (blockIdx.x == 0 && t == 0 && iter > 0) {
            float df = g_diff;
            if (!g_done && sqrtf(df) < 1e-8f) g_done = 1;
            g_diff = 0.f;
        }

        // ---- load next pass's C image + c2 (consumed at first-tile cp_wait0) ----
        if (iter < 25) {
            #pragma unroll
            for (int k = 0; k < 2; k++) {
                int c = t + k * THREADS;   // 0..511 chunks of 16B
                cp_async16(sb + OFF_CH + c * 16, (const char*)gCimg + c * 16);
            }
            if (t < 16) cp_async16(sb + OFF_C2 + t * 16, (const char*)gc2 + t * 16);
            cp_commit();
        }
    }

    // ---- final: if never converged, answer is C_25 ----
    if (blockIdx.x == 0) {
        __syncthreads();   // t0's g_done update visible to whole block
        if (!g_done)
            for (int i = t; i < 4096; i += THREADS) out[i] = __ldcg(&g_C[1][i]);
    }
}

// ---------------- host launch ----------------
extern "C" void kernel_launch(void* const* d_in, const int* in_sizes, int n_in,
                              void* d_out, int out_size) {
    const float* data = (const float*)d_in[0];
    const float* u0   = (const float*)d_in[1];
    const int N = in_sizes[0] / 64;     // 300000
    float* out = (float*)d_out;
    const int ntiles = (N + 127) >> 7;

    cudaFuncSetAttribute(fcm_persist, cudaFuncAttributeMaxDynamicSharedMemorySize, SMEM_BYTES);

    int nbsm = 0;
    cudaOccupancyMaxActiveBlocksPerMultiprocessor(&nbsm, fcm_persist, THREADS, SMEM_BYTES);
    if (nbsm < 1) nbsm = 1;
    if (nbsm > 3) nbsm = 3;
    int dev = 0, nsm = 148;
    cudaGetDevice(&dev);
    cudaDeviceGetAttribute(&nsm, cudaDevAttrMultiProcessorCount, dev);
    int grid = nbsm * nsm;   // all CTAs co-resident -> software grid barrier is safe
    if (grid > MAXBLK) grid = MAXBLK;

    fcm_pre<<<grid, THREADS>>>(data, N, ntiles);
    fcm_persist<<<grid, THREADS, SMEM_BYTES>>>(u0, N, out);
}